// round 3
// baseline (speedup 1.0000x reference)
#include <cuda_runtime.h>

// Problem constants
#define BN 4
#define TN 2048
#define DN 1024
#define HN 16
#define HDN 64
#define MROWS (BN * TN)   // 8192

// Scratch (static device arrays: no runtime allocation allowed)
__device__ float g_Q[(size_t)BN * HN * TN * HDN];   // [b,h,t,hd]
__device__ float g_K[(size_t)BN * HN * TN * HDN];
__device__ float g_V[(size_t)BN * HN * TN * HDN];
__device__ float g_att[(size_t)BN * TN * DN];       // [b,t,h*hd+dh]

// ---------------------------------------------------------------------------
// SGEMM body: C[128x128] = A[128xK] * W[128xK]^T  (both row-major, K=1024)
// 256 threads, 8x8 micro-tile per thread with strided (t + 16*i) mapping so
// smem reads are broadcast (A) / conflict-free consecutive banks (B).
// ---------------------------------------------------------------------------
__device__ __forceinline__ void sgemm_body(const float* __restrict__ A,
                                           const float* __restrict__ W,
                                           float (&c)[8][8],
                                           float (*Ast)[132],
                                           float (*Bst)[132]) {
    const int tid = threadIdx.x;
    const int ty = tid >> 4, tx = tid & 15;
    const int m0 = blockIdx.y * 128, n0 = blockIdx.x * 128;
    // two float4 slots per thread for each tile (512 slots of float4 = 128x16)
    const int r0 = tid >> 2;          // 0..63
    const int r1 = r0 + 64;           // 64..127
    const int v0 = tid & 3;           // which float4 in the 16-wide k strip

#pragma unroll
    for (int i = 0; i < 8; i++)
#pragma unroll
        for (int j = 0; j < 8; j++) c[i][j] = 0.f;

    for (int k0 = 0; k0 < DN; k0 += 16) {
        float4 a0 = *(const float4*)(A + (size_t)(m0 + r0) * DN + k0 + v0 * 4);
        float4 a1 = *(const float4*)(A + (size_t)(m0 + r1) * DN + k0 + v0 * 4);
        float4 w0 = *(const float4*)(W + (size_t)(n0 + r0) * DN + k0 + v0 * 4);
        float4 w1 = *(const float4*)(W + (size_t)(n0 + r1) * DN + k0 + v0 * 4);
        __syncthreads();   // previous iteration's reads done before overwrite
        Ast[v0 * 4 + 0][r0] = a0.x; Ast[v0 * 4 + 1][r0] = a0.y;
        Ast[v0 * 4 + 2][r0] = a0.z; Ast[v0 * 4 + 3][r0] = a0.w;
        Ast[v0 * 4 + 0][r1] = a1.x; Ast[v0 * 4 + 1][r1] = a1.y;
        Ast[v0 * 4 + 2][r1] = a1.z; Ast[v0 * 4 + 3][r1] = a1.w;
        Bst[v0 * 4 + 0][r0] = w0.x; Bst[v0 * 4 + 1][r0] = w0.y;
        Bst[v0 * 4 + 2][r0] = w0.z; Bst[v0 * 4 + 3][r0] = w0.w;
        Bst[v0 * 4 + 0][r1] = w1.x; Bst[v0 * 4 + 1][r1] = w1.y;
        Bst[v0 * 4 + 2][r1] = w1.z; Bst[v0 * 4 + 3][r1] = w1.w;
        __syncthreads();
#pragma unroll
        for (int kk = 0; kk < 16; kk++) {
            float a[8], b[8];
#pragma unroll
            for (int i = 0; i < 8; i++) a[i] = Ast[kk][ty + 16 * i];
#pragma unroll
            for (int j = 0; j < 8; j++) b[j] = Bst[kk][tx + 16 * j];
#pragma unroll
            for (int i = 0; i < 8; i++)
#pragma unroll
                for (int j = 0; j < 8; j++)
                    c[i][j] = fmaf(a[i], b[j], c[i][j]);
        }
    }
}

// K1: Q/K/V = x @ W^T + b, written in [b,h,t,hd] layout. blockIdx.z selects.
__global__ void __launch_bounds__(256)
gemm_qkv_kernel(const float* __restrict__ x,
                const float* __restrict__ Wq, const float* __restrict__ bq,
                const float* __restrict__ Wk, const float* __restrict__ bk,
                const float* __restrict__ Wv, const float* __restrict__ bv) {
    __shared__ float Ast[16][132];
    __shared__ float Bst[16][132];
    const int z = blockIdx.z;
    const float* W    = (z == 0) ? Wq : (z == 1) ? Wk : Wv;
    const float* bias = (z == 0) ? bq : (z == 1) ? bk : bv;
    float* out        = (z == 0) ? g_Q : (z == 1) ? g_K : g_V;

    float c[8][8];
    sgemm_body(x, W, c, Ast, Bst);

    const int tid = threadIdx.x;
    const int ty = tid >> 4, tx = tid & 15;
    const int m0 = blockIdx.y * 128, n0 = blockIdx.x * 128;
#pragma unroll
    for (int i = 0; i < 8; i++) {
        const int m = m0 + ty + 16 * i;
        const int b = m >> 11;         // m / TN
        const int t = m & (TN - 1);
#pragma unroll
        for (int j = 0; j < 8; j++) {
            const int n = n0 + tx + 16 * j;
            const int h = n >> 6;      // n / HDN
            const int dh = n & (HDN - 1);
            out[(((size_t)(b * HN + h)) * TN + t) * HDN + dh] = c[i][j] + bias[n];
        }
    }
}

// K3: out = g_att @ Wo^T + bo   ([8192,1024] row-major output)
__global__ void __launch_bounds__(256)
gemm_out_kernel(const float* __restrict__ Wo, const float* __restrict__ bo,
                float* __restrict__ out) {
    __shared__ float Ast[16][132];
    __shared__ float Bst[16][132];
    float c[8][8];
    sgemm_body(g_att, Wo, c, Ast, Bst);

    const int tid = threadIdx.x;
    const int ty = tid >> 4, tx = tid & 15;
    const int m0 = blockIdx.y * 128, n0 = blockIdx.x * 128;
#pragma unroll
    for (int i = 0; i < 8; i++) {
        const int m = m0 + ty + 16 * i;
#pragma unroll
        for (int j = 0; j < 8; j++) {
            const int n = n0 + tx + 16 * j;
            out[(size_t)m * DN + n] = c[i][j] + bo[n];
        }
    }
}

// ---------------------------------------------------------------------------
// K2: streaming-softmax attention.
// Block = (b,h, 64-row q tile). 256 threads, 4x4 micro-tiles with strided
// (t + 16*i) row/col mapping (conflict-free smem access). K and V share one
// smem tile buffer (K for S=QK^T, then V for O+=PV).
// ---------------------------------------------------------------------------
__global__ void __launch_bounds__(256)
attn_kernel(const float* __restrict__ relbias) {
    extern __shared__ float sm[];
    float* Qs   = sm;                  // 64*65
    float* KVs  = Qs + 64 * 65;        // 64*65
    float* Ps   = KVs + 64 * 65;       // 64*65
    float* m_sm = Ps + 64 * 65;        // 64
    float* l_sm = m_sm + 64;           // 64
    float* bsm  = l_sm + 64;           // 31

    const int tid = threadIdx.x;
    const int ty = tid >> 4, tx = tid & 15;
    const int bh = blockIdx.y;                 // b*HN + h
    const int h  = bh & (HN - 1);
    const int q0 = blockIdx.x * 64;

    const float* Qg = g_Q + ((size_t)bh * TN + q0) * HDN;
    const float* Kg = g_K + (size_t)bh * TN * HDN;
    const float* Vg = g_V + (size_t)bh * TN * HDN;

    // Load Q tile (64x64 floats = 1024 float4)
    for (int i = tid; i < 1024; i += 256) {
        const int r = i >> 4, v = i & 15;
        float4 f = *(const float4*)(Qg + r * HDN + v * 4);
        float* d = &Qs[r * 65 + v * 4];
        d[0] = f.x; d[1] = f.y; d[2] = f.z; d[3] = f.w;
    }
    if (tid < 64) { m_sm[tid] = -1e30f; l_sm[tid] = 0.f; }
    if (tid < 31) bsm[tid] = relbias[tid * HN + h];

    float oc[4][4];
#pragma unroll
    for (int i = 0; i < 4; i++)
#pragma unroll
        for (int j = 0; j < 4; j++) oc[i][j] = 0.f;

    for (int kt = 0; kt < TN; kt += 64) {
        __syncthreads();                       // prior PV reads of KVs done
        // Load K tile
        for (int i = tid; i < 1024; i += 256) {
            const int r = i >> 4, v = i & 15;
            float4 f = *(const float4*)(Kg + (size_t)(kt + r) * HDN + v * 4);
            float* d = &KVs[r * 65 + v * 4];
            d[0] = f.x; d[1] = f.y; d[2] = f.z; d[3] = f.w;
        }
        __syncthreads();

        // S = Q K^T  (raw dot products)
        float s[4][4];
#pragma unroll
        for (int i = 0; i < 4; i++)
#pragma unroll
            for (int j = 0; j < 4; j++) s[i][j] = 0.f;
#pragma unroll 4
        for (int d = 0; d < HDN; d++) {
            float a[4], b[4];
#pragma unroll
            for (int i = 0; i < 4; i++) a[i] = Qs[(ty + 16 * i) * 65 + d];
#pragma unroll
            for (int j = 0; j < 4; j++) b[j] = KVs[(tx + 16 * j) * 65 + d];
#pragma unroll
            for (int i = 0; i < 4; i++)
#pragma unroll
                for (int j = 0; j < 4; j++)
                    s[i][j] = fmaf(a[i], b[j], s[i][j]);
        }
        __syncthreads();                       // done reading K tile

        // Load V tile into the same buffer (reads happen after next barrier)
        for (int i = tid; i < 1024; i += 256) {
            const int r = i >> 4, v = i & 15;
            float4 f = *(const float4*)(Vg + (size_t)(kt + r) * HDN + v * 4);
            float* d = &KVs[r * 65 + v * 4];
            d[0] = f.x; d[1] = f.y; d[2] = f.z; d[3] = f.w;
        }

        // Online softmax on register tile (exp spread over all 256 threads)
#pragma unroll
        for (int i = 0; i < 4; i++) {
            const int row = ty + 16 * i;
            const int qg = q0 + row;
            float sv[4];
            float rm = -1e30f;
#pragma unroll
            for (int j = 0; j < 4; j++) {
                const int kg = kt + tx + 16 * j;
                int rel = kg - qg;
                rel = rel < -15 ? -15 : (rel > 15 ? 15 : rel);
                const float val = s[i][j] * 0.125f + bsm[rel + 15];
                sv[j] = val;
                rm = fmaxf(rm, val);
            }
#pragma unroll
            for (int off = 1; off < 16; off <<= 1)
                rm = fmaxf(rm, __shfl_xor_sync(0xffffffffu, rm, off));
            const float mprev = m_sm[row];
            const float newm = fmaxf(mprev, rm);
            const float scl = __expf(mprev - newm);
            float rs = 0.f;
#pragma unroll
            for (int j = 0; j < 4; j++) {
                const float p = __expf(sv[j] - newm);
                Ps[row * 65 + tx + 16 * j] = p;
                rs += p;
            }
#pragma unroll
            for (int off = 1; off < 16; off <<= 1)
                rs += __shfl_xor_sync(0xffffffffu, rs, off);
#pragma unroll
            for (int j = 0; j < 4; j++) oc[i][j] *= scl;
            if (tx == 0) {
                m_sm[row] = newm;
                l_sm[row] = l_sm[row] * scl + rs;
            }
        }
        __syncthreads();                       // P stores + V stores visible

        // O += P V
#pragma unroll 4
        for (int kk = 0; kk < 64; kk++) {
            float a[4], b[4];
#pragma unroll
            for (int i = 0; i < 4; i++) a[i] = Ps[(ty + 16 * i) * 65 + kk];
#pragma unroll
            for (int j = 0; j < 4; j++) b[j] = KVs[kk * 65 + tx + 16 * j];
#pragma unroll
            for (int i = 0; i < 4; i++)
#pragma unroll
                for (int j = 0; j < 4; j++)
                    oc[i][j] = fmaf(a[i], b[j], oc[i][j]);
        }
    }
    __syncthreads();

    // Finalize: divide by l, write [b,t,h*hd+dh] for the output projection
    const int b_ = bh >> 4;
#pragma unroll
    for (int i = 0; i < 4; i++) {
        const int row = ty + 16 * i;
        const float inv = 1.f / l_sm[row];
        const int t = q0 + row;
#pragma unroll
        for (int j = 0; j < 4; j++) {
            g_att[((size_t)(b_ * TN + t)) * DN + h * HDN + tx + 16 * j] =
                oc[i][j] * inv;
        }
    }
}

// ---------------------------------------------------------------------------
extern "C" void kernel_launch(void* const* d_in, const int* in_sizes, int n_in,
                              void* d_out, int out_size) {
    const float* x  = (const float*)d_in[0];
    const float* Wq = (const float*)d_in[1];
    const float* bq = (const float*)d_in[2];
    const float* Wk = (const float*)d_in[3];
    const float* bk = (const float*)d_in[4];
    const float* Wv = (const float*)d_in[5];
    const float* bv = (const float*)d_in[6];
    const float* rb = (const float*)d_in[7];
    const float* Wo = (const float*)d_in[8];
    const float* bo = (const float*)d_in[9];
    float* out = (float*)d_out;

    const size_t attn_smem = (3 * 64 * 65 + 64 + 64 + 32) * sizeof(float);
    cudaFuncSetAttribute(attn_kernel,
                         cudaFuncAttributeMaxDynamicSharedMemorySize,
                         (int)attn_smem);

    gemm_qkv_kernel<<<dim3(DN / 128, MROWS / 128, 3), 256>>>(x, Wq, bq, Wk, bk,
                                                             Wv, bv);
    attn_kernel<<<dim3(TN / 64, BN * HN), 256, attn_smem>>>(rb);
    gemm_out_kernel<<<dim3(DN / 128, MROWS / 128), 256>>>(Wo, bo, out);
}

// round 5
// speedup vs baseline: 1.3843x; 1.3843x over previous
#include <cuda_runtime.h>
#include <cuda_bf16.h>
#include <cstdint>

// Problem constants
#define BN 4
#define TN 2048
#define DN 1024
#define HN 16
#define HDN 64
#define MROWS (BN * TN)   // 8192

// HMMA GEMM tiling: CTA 128x128, K-chunk 32, double-buffered smem
#define KC 32
#define NCH (DN / KC)          // 32
#define ASTR 40                // smem row stride in bf16 (32 data + 8 pad)
#define TILE_E (128 * ASTR)    // elems per 128x32 tile (padded)
#define STAGE_E (4 * TILE_E)   // Ah, Al, Bh, Bl
#define SMEM_B (2 * STAGE_E * 2)  // bytes (two stages)

// ---------------------------------------------------------------------------
__device__ __forceinline__ uint32_t smem_to_u32(const void* p) {
    uint32_t a;
    asm("{ .reg .u64 t; cvta.to.shared.u64 t, %1; cvt.u32.u64 %0, t; }" : "=r"(a) : "l"(p));
    return a;
}
__device__ __forceinline__ void ldm_x4(uint32_t* r, uint32_t a) {
    asm volatile("ldmatrix.sync.aligned.m8n8.x4.shared.b16 {%0,%1,%2,%3}, [%4];"
                 : "=r"(r[0]), "=r"(r[1]), "=r"(r[2]), "=r"(r[3]) : "r"(a));
}
__device__ __forceinline__ void ldm_x2(uint32_t* r, uint32_t a) {
    asm volatile("ldmatrix.sync.aligned.m8n8.x2.shared.b16 {%0,%1}, [%2];"
                 : "=r"(r[0]), "=r"(r[1]) : "r"(a));
}
__device__ __forceinline__ void mma_bf16(float* c, const uint32_t* a, const uint32_t* b) {
    asm volatile(
        "mma.sync.aligned.m16n8k16.row.col.f32.bf16.bf16.f32 "
        "{%0,%1,%2,%3}, {%4,%5,%6,%7}, {%8,%9}, {%0,%1,%2,%3};"
        : "+f"(c[0]), "+f"(c[1]), "+f"(c[2]), "+f"(c[3])
        : "r"(a[0]), "r"(a[1]), "r"(a[2]), "r"(a[3]), "r"(b[0]), "r"(b[1]));
}

// ---------------------------------------------------------------------------
// Device scratch (static: no runtime allocation allowed)
// ---------------------------------------------------------------------------
__device__ __nv_bfloat16 g_xh[(size_t)MROWS * DN];
__device__ __nv_bfloat16 g_xl[(size_t)MROWS * DN];
__device__ __nv_bfloat16 g_Wh[3][(size_t)DN * DN];   // Wq, Wk, Wv hi
__device__ __nv_bfloat16 g_Wl[3][(size_t)DN * DN];
__device__ __nv_bfloat16 g_Woh[(size_t)DN * DN];
__device__ __nv_bfloat16 g_Wol[(size_t)DN * DN];
__device__ __nv_bfloat16 g_ah[(size_t)MROWS * DN];   // attention output hi/lo
__device__ __nv_bfloat16 g_al[(size_t)MROWS * DN];
__device__ float g_Q[(size_t)BN * HN * TN * HDN];    // [b,h,t,hd]
__device__ float g_K[(size_t)BN * HN * TN * HDN];
__device__ float g_V[(size_t)BN * HN * TN * HDN];

// ---------------------------------------------------------------------------
// fp32 -> (bf16 hi, bf16 lo) split conversion
// ---------------------------------------------------------------------------
__global__ void convert_kernel(const float* __restrict__ src, int which, int n4) {
    __nv_bfloat16 *hi, *lo;
    switch (which) {
        case 0: hi = g_xh;    lo = g_xl;    break;
        case 1: hi = g_Wh[0]; lo = g_Wl[0]; break;
        case 2: hi = g_Wh[1]; lo = g_Wl[1]; break;
        case 3: hi = g_Wh[2]; lo = g_Wl[2]; break;
        default: hi = g_Woh;  lo = g_Wol;   break;
    }
    int i = blockIdx.x * blockDim.x + threadIdx.x;
    if (i >= n4) return;
    float4 v = ((const float4*)src)[i];
    float vv[4] = {v.x, v.y, v.z, v.w};
#pragma unroll
    for (int t = 0; t < 4; t++) {
        __nv_bfloat16 h = __float2bfloat16(vv[t]);
        hi[4 * i + t] = h;
        lo[4 * i + t] = __float2bfloat16(vv[t] - __bfloat162float(h));
    }
}

// ---------------------------------------------------------------------------
// HMMA GEMM: C[128x128] = A @ B^T + bias, A/B as bf16 hi/lo pairs,
// 3-term split accumulation into fp32 mma accumulators.
// MODE 0: qkv (blockIdx.z selects weight; scatter to [b,h,t,hd])
// MODE 1: out projection (row-major [8192,1024])
// ---------------------------------------------------------------------------
template <int MODE>
__global__ void __launch_bounds__(256)
hmma_gemm_kernel(const float* __restrict__ b0, const float* __restrict__ b1,
                 const float* __restrict__ b2, float* __restrict__ outp) {
    extern __shared__ __nv_bfloat16 dsm[];
    const uint32_t sbase = smem_to_u32(dsm);
    const int tid = threadIdx.x;
    const int w = tid >> 5, lane = tid & 31;
    const int warp_m = w >> 2, warp_n = w & 3;   // 2 x 4 warp grid

    const __nv_bfloat16 *Ah, *Al, *Bh, *Bl;
    const float* bias;
    float* dst;
    if (MODE == 0) {
        const int z = blockIdx.z;
        Ah = g_xh; Al = g_xl; Bh = g_Wh[z]; Bl = g_Wl[z];
        bias = (z == 0) ? b0 : (z == 1) ? b1 : b2;
        dst = (z == 0) ? g_Q : (z == 1) ? g_K : g_V;
    } else {
        Ah = g_ah; Al = g_al; Bh = g_Woh; Bl = g_Wol;
        bias = b0; dst = outp;
    }
    const int m0 = blockIdx.y * 128, n0 = blockIdx.x * 128;

    const __nv_bfloat16* gsrc[4] = {Ah, Al, Bh, Bl};
    const int rbase[4] = {m0, m0, n0, n0};

    float acc[4][4][4];
#pragma unroll
    for (int mi = 0; mi < 4; mi++)
#pragma unroll
        for (int ni = 0; ni < 4; ni++)
#pragma unroll
            for (int q = 0; q < 4; q++) acc[mi][ni][q] = 0.f;

    // per-chunk staging registers: 4 tiles x 2 iters x 16B
    uint4 st[8];
    const int ld_row = tid >> 2;     // 0..63 (per iter; iter adds 64)
    const int ld_q   = tid & 3;      // 16B unit within 64B row

#define LOAD_G(c)                                                               \
    {                                                                           \
        _Pragma("unroll")                                                       \
        for (int t4 = 0; t4 < 4; t4++) {                                        \
            _Pragma("unroll")                                                   \
            for (int it = 0; it < 2; it++) {                                    \
                const int row = ld_row + it * 64;                               \
                st[t4 * 2 + it] = *(const uint4*)(gsrc[t4] +                    \
                    (size_t)(rbase[t4] + row) * DN + (c) * KC + ld_q * 8);      \
            }                                                                   \
        }                                                                       \
    }
#define STORE_S(s)                                                              \
    {                                                                           \
        _Pragma("unroll")                                                       \
        for (int t4 = 0; t4 < 4; t4++) {                                        \
            _Pragma("unroll")                                                   \
            for (int it = 0; it < 2; it++) {                                    \
                const int row = ld_row + it * 64;                               \
                *(uint4*)(dsm + (size_t)(s) * STAGE_E + t4 * TILE_E +           \
                          row * ASTR + ld_q * 8) = st[t4 * 2 + it];             \
            }                                                                   \
        }                                                                       \
    }

    LOAD_G(0);
    STORE_S(0);
    __syncthreads();

    const int a_row = warp_m * 64 + (lane & 15);
    const int a_koff = ((lane >> 4) & 1) * 8;
    const int b_row = warp_n * 32 + (lane & 7);
    const int b_koff = ((lane >> 3) & 1) * 8;

    for (int c = 0; c < NCH; c++) {
        if (c + 1 < NCH) LOAD_G(c + 1);
        const uint32_t sb = sbase + (uint32_t)(c & 1) * (STAGE_E * 2);
#pragma unroll
        for (int ks = 0; ks < 2; ks++) {
            uint32_t ah[4][4], al[4][4], bh[4][2], bl[4][2];
#pragma unroll
            for (int mi = 0; mi < 4; mi++) {
                const uint32_t ad = sb +
                    (uint32_t)(((a_row + mi * 16) * ASTR + ks * 16 + a_koff) * 2);
                ldm_x4(ah[mi], ad);
                ldm_x4(al[mi], ad + TILE_E * 2);
            }
#pragma unroll
            for (int ni = 0; ni < 4; ni++) {
                const uint32_t bd = sb + 2 * TILE_E * 2 +
                    (uint32_t)(((b_row + ni * 8) * ASTR + ks * 16 + b_koff) * 2);
                ldm_x2(bh[ni], bd);
                ldm_x2(bl[ni], bd + TILE_E * 2);
            }
#pragma unroll
            for (int mi = 0; mi < 4; mi++)
#pragma unroll
                for (int ni = 0; ni < 4; ni++) {
                    mma_bf16(acc[mi][ni], ah[mi], bh[ni]);
                    mma_bf16(acc[mi][ni], ah[mi], bl[ni]);
                    mma_bf16(acc[mi][ni], al[mi], bh[ni]);
                }
        }
        __syncthreads();
        if (c + 1 < NCH) {
            STORE_S((c + 1) & 1);
            __syncthreads();
        }
    }

    // Epilogue: c-fragment (g = lane/4, pair cols 2*(lane%4)) + bias, scatter
    const int g = lane >> 2;
    const int cp = (lane & 3) * 2;
#pragma unroll
    for (int mi = 0; mi < 4; mi++) {
#pragma unroll
        for (int ni = 0; ni < 4; ni++) {
            const int col = n0 + warp_n * 32 + ni * 8 + cp;
            const float bx = bias[col], by = bias[col + 1];
#pragma unroll
            for (int half = 0; half < 2; half++) {
                const int m = m0 + warp_m * 64 + mi * 16 + g + half * 8;
                float2 v;
                v.x = acc[mi][ni][half * 2 + 0] + bx;
                v.y = acc[mi][ni][half * 2 + 1] + by;
                if (MODE == 0) {
                    const int b = m >> 11, t = m & (TN - 1);
                    const int h = col >> 6, dh = col & 63;
                    *(float2*)(dst + (((size_t)(b * HN + h)) * TN + t) * HDN + dh) = v;
                } else {
                    *(float2*)(dst + (size_t)m * DN + col) = v;
                }
            }
        }
    }
#undef LOAD_G
#undef STORE_S
}

// ---------------------------------------------------------------------------
// K2: streaming-softmax attention (fp32); epilogue emits bf16 hi/lo pairs
// for the tensor-core output projection.
// ---------------------------------------------------------------------------
__global__ void __launch_bounds__(256)
attn_kernel(const float* __restrict__ relbias) {
    extern __shared__ float sm[];
    float* Qs   = sm;                  // 64*65
    float* KVs  = Qs + 64 * 65;        // 64*65
    float* Ps   = KVs + 64 * 65;       // 64*65
    float* m_sm = Ps + 64 * 65;        // 64
    float* l_sm = m_sm + 64;           // 64
    float* bsm  = l_sm + 64;           // 31

    const int tid = threadIdx.x;
    const int ty = tid >> 4, tx = tid & 15;
    const int bh = blockIdx.y;                 // b*HN + h
    const int h  = bh & (HN - 1);
    const int q0 = blockIdx.x * 64;

    const float* Qg = g_Q + ((size_t)bh * TN + q0) * HDN;
    const float* Kg = g_K + (size_t)bh * TN * HDN;
    const float* Vg = g_V + (size_t)bh * TN * HDN;

    for (int i = tid; i < 1024; i += 256) {
        const int r = i >> 4, v = i & 15;
        float4 f = *(const float4*)(Qg + r * HDN + v * 4);
        float* d = &Qs[r * 65 + v * 4];
        d[0] = f.x; d[1] = f.y; d[2] = f.z; d[3] = f.w;
    }
    if (tid < 64) { m_sm[tid] = -1e30f; l_sm[tid] = 0.f; }
    if (tid < 31) bsm[tid] = relbias[tid * HN + h];

    float oc[4][4];
#pragma unroll
    for (int i = 0; i < 4; i++)
#pragma unroll
        for (int j = 0; j < 4; j++) oc[i][j] = 0.f;

    for (int kt = 0; kt < TN; kt += 64) {
        __syncthreads();
        for (int i = tid; i < 1024; i += 256) {
            const int r = i >> 4, v = i & 15;
            float4 f = *(const float4*)(Kg + (size_t)(kt + r) * HDN + v * 4);
            float* d = &KVs[r * 65 + v * 4];
            d[0] = f.x; d[1] = f.y; d[2] = f.z; d[3] = f.w;
        }
        __syncthreads();

        float s[4][4];
#pragma unroll
        for (int i = 0; i < 4; i++)
#pragma unroll
            for (int j = 0; j < 4; j++) s[i][j] = 0.f;
#pragma unroll 4
        for (int d = 0; d < HDN; d++) {
            float a[4], b[4];
#pragma unroll
            for (int i = 0; i < 4; i++) a[i] = Qs[(ty + 16 * i) * 65 + d];
#pragma unroll
            for (int j = 0; j < 4; j++) b[j] = KVs[(tx + 16 * j) * 65 + d];
#pragma unroll
            for (int i = 0; i < 4; i++)
#pragma unroll
                for (int j = 0; j < 4; j++)
                    s[i][j] = fmaf(a[i], b[j], s[i][j]);
        }
        __syncthreads();

        for (int i = tid; i < 1024; i += 256) {
            const int r = i >> 4, v = i & 15;
            float4 f = *(const float4*)(Vg + (size_t)(kt + r) * HDN + v * 4);
            float* d = &KVs[r * 65 + v * 4];
            d[0] = f.x; d[1] = f.y; d[2] = f.z; d[3] = f.w;
        }

#pragma unroll
        for (int i = 0; i < 4; i++) {
            const int row = ty + 16 * i;
            const int qg = q0 + row;
            float sv[4];
            float rm = -1e30f;
#pragma unroll
            for (int j = 0; j < 4; j++) {
                const int kg = kt + tx + 16 * j;
                int rel = kg - qg;
                rel = rel < -15 ? -15 : (rel > 15 ? 15 : rel);
                const float val = s[i][j] * 0.125f + bsm[rel + 15];
                sv[j] = val;
                rm = fmaxf(rm, val);
            }
#pragma unroll
            for (int off = 1; off < 16; off <<= 1)
                rm = fmaxf(rm, __shfl_xor_sync(0xffffffffu, rm, off));
            const float mprev = m_sm[row];
            const float newm = fmaxf(mprev, rm);
            const float scl = __expf(mprev - newm);
            float rs = 0.f;
#pragma unroll
            for (int j = 0; j < 4; j++) {
                const float p = __expf(sv[j] - newm);
                Ps[row * 65 + tx + 16 * j] = p;
                rs += p;
            }
#pragma unroll
            for (int off = 1; off < 16; off <<= 1)
                rs += __shfl_xor_sync(0xffffffffu, rs, off);
#pragma unroll
            for (int j = 0; j < 4; j++) oc[i][j] *= scl;
            if (tx == 0) {
                m_sm[row] = newm;
                l_sm[row] = l_sm[row] * scl + rs;
            }
        }
        __syncthreads();

#pragma unroll 4
        for (int kk = 0; kk < 64; kk++) {
            float a[4], b[4];
#pragma unroll
            for (int i = 0; i < 4; i++) a[i] = Ps[(ty + 16 * i) * 65 + kk];
#pragma unroll
            for (int j = 0; j < 4; j++) b[j] = KVs[kk * 65 + tx + 16 * j];
#pragma unroll
            for (int i = 0; i < 4; i++)
#pragma unroll
                for (int j = 0; j < 4; j++)
                    oc[i][j] = fmaf(a[i], b[j], oc[i][j]);
        }
    }
    __syncthreads();

    // Finalize: divide by l, emit bf16 hi/lo in [b,t,h*hd+dh] layout
    const int b_ = bh >> 4;
#pragma unroll
    for (int i = 0; i < 4; i++) {
        const int row = ty + 16 * i;
        const float inv = 1.f / l_sm[row];
        const int t = q0 + row;
#pragma unroll
        for (int j = 0; j < 4; j++) {
            const float v = oc[i][j] * inv;
            const size_t idx =
                ((size_t)(b_ * TN + t)) * DN + h * HDN + tx + 16 * j;
            const __nv_bfloat16 hv = __float2bfloat16(v);
            g_ah[idx] = hv;
            g_al[idx] = __float2bfloat16(v - __bfloat162float(hv));
        }
    }
}

// ---------------------------------------------------------------------------
extern "C" void kernel_launch(void* const* d_in, const int* in_sizes, int n_in,
                              void* d_out, int out_size) {
    const float* x  = (const float*)d_in[0];
    const float* Wq = (const float*)d_in[1];
    const float* bq = (const float*)d_in[2];
    const float* Wk = (const float*)d_in[3];
    const float* bk = (const float*)d_in[4];
    const float* Wv = (const float*)d_in[5];
    const float* bv = (const float*)d_in[6];
    const float* rb = (const float*)d_in[7];
    const float* Wo = (const float*)d_in[8];
    const float* bo = (const float*)d_in[9];
    float* out = (float*)d_out;

    cudaFuncSetAttribute(hmma_gemm_kernel<0>,
                         cudaFuncAttributeMaxDynamicSharedMemorySize, SMEM_B);
    cudaFuncSetAttribute(hmma_gemm_kernel<1>,
                         cudaFuncAttributeMaxDynamicSharedMemorySize, SMEM_B);
    const size_t attn_smem = (3 * 64 * 65 + 64 + 64 + 32) * sizeof(float);
    cudaFuncSetAttribute(attn_kernel,
                         cudaFuncAttributeMaxDynamicSharedMemorySize,
                         (int)attn_smem);

    // fp32 -> bf16 hi/lo splits
    convert_kernel<<<(MROWS * DN / 4 + 255) / 256, 256>>>(x, 0, MROWS * DN / 4);
    convert_kernel<<<(DN * DN / 4 + 255) / 256, 256>>>(Wq, 1, DN * DN / 4);
    convert_kernel<<<(DN * DN / 4 + 255) / 256, 256>>>(Wk, 2, DN * DN / 4);
    convert_kernel<<<(DN * DN / 4 + 255) / 256, 256>>>(Wv, 3, DN * DN / 4);
    convert_kernel<<<(DN * DN / 4 + 255) / 256, 256>>>(Wo, 4, DN * DN / 4);

    // QKV projections on HMMA tensor cores
    hmma_gemm_kernel<0><<<dim3(DN / 128, MROWS / 128, 3), 256, SMEM_B>>>(
        bq, bk, bv, nullptr);
    // fp32 flash attention (emits bf16 hi/lo)
    attn_kernel<<<dim3(TN / 64, BN * HN), 256, attn_smem>>>(rb);
    // Output projection on HMMA tensor cores
    hmma_gemm_kernel<1><<<dim3(DN / 128, MROWS / 128), 256, SMEM_B>>>(
        bo, nullptr, nullptr, out);
}

// round 6
// speedup vs baseline: 2.8406x; 2.0520x over previous
#include <cuda_runtime.h>
#include <cuda_bf16.h>
#include <cstdint>

// Problem constants
#define BN 4
#define TN 2048
#define DN 1024
#define HN 16
#define HDN 64
#define MROWS (BN * TN)   // 8192

// HMMA GEMM tiling: CTA 128x128, K-chunk 32, double-buffered smem
#define KC 32
#define NCH (DN / KC)          // 32
#define ASTR 40                // smem row stride in bf16 (32 data + 8 pad)
#define TILE_E (128 * ASTR)    // elems per 128x32 tile (padded)
#define STAGE_E (4 * TILE_E)   // Ah, Al, Bh, Bl
#define SMEM_B (2 * STAGE_E * 2)  // bytes (two stages)

// Attention tiling
#define QT 128                 // q rows per CTA
#define KTILE 64               // kv rows per iteration
#define KSTR 72                // smem row stride in bf16 (64 + 8 pad; 144B = 9x16B)
#define ATILE_B (KTILE * KSTR * 2)   // 9216 bytes per 64x64 tile
#define ATTN_SMEM (4 * ATILE_B + 128)

// ---------------------------------------------------------------------------
__device__ __forceinline__ uint32_t smem_to_u32(const void* p) {
    uint32_t a;
    asm("{ .reg .u64 t; cvta.to.shared.u64 t, %1; cvt.u32.u64 %0, t; }" : "=r"(a) : "l"(p));
    return a;
}
__device__ __forceinline__ void ldm_x4(uint32_t* r, uint32_t a) {
    asm volatile("ldmatrix.sync.aligned.m8n8.x4.shared.b16 {%0,%1,%2,%3}, [%4];"
                 : "=r"(r[0]), "=r"(r[1]), "=r"(r[2]), "=r"(r[3]) : "r"(a));
}
__device__ __forceinline__ void ldm_x4t(uint32_t* r, uint32_t a) {
    asm volatile("ldmatrix.sync.aligned.m8n8.x4.trans.shared.b16 {%0,%1,%2,%3}, [%4];"
                 : "=r"(r[0]), "=r"(r[1]), "=r"(r[2]), "=r"(r[3]) : "r"(a));
}
__device__ __forceinline__ void mma_bf16(float* c, const uint32_t* a, const uint32_t* b) {
    asm volatile(
        "mma.sync.aligned.m16n8k16.row.col.f32.bf16.bf16.f32 "
        "{%0,%1,%2,%3}, {%4,%5,%6,%7}, {%8,%9}, {%0,%1,%2,%3};"
        : "+f"(c[0]), "+f"(c[1]), "+f"(c[2]), "+f"(c[3])
        : "r"(a[0]), "r"(a[1]), "r"(a[2]), "r"(a[3]), "r"(b[0]), "r"(b[1]));
}

// ---------------------------------------------------------------------------
// Device scratch (static: no runtime allocation allowed)
// ---------------------------------------------------------------------------
__device__ __nv_bfloat16 g_xh[(size_t)MROWS * DN];
__device__ __nv_bfloat16 g_xl[(size_t)MROWS * DN];
__device__ __nv_bfloat16 g_Wh[3][(size_t)DN * DN];   // Wq, Wk, Wv hi
__device__ __nv_bfloat16 g_Wl[3][(size_t)DN * DN];
__device__ __nv_bfloat16 g_Woh[(size_t)DN * DN];
__device__ __nv_bfloat16 g_Wol[(size_t)DN * DN];
__device__ __nv_bfloat16 g_ah[(size_t)MROWS * DN];   // attention output hi/lo
__device__ __nv_bfloat16 g_al[(size_t)MROWS * DN];
__device__ __nv_bfloat16 g_QKVh[3][(size_t)MROWS * DN];  // [b,h,t,hd] hi
__device__ __nv_bfloat16 g_QKVl[3][(size_t)MROWS * DN];  // [b,h,t,hd] lo

// ---------------------------------------------------------------------------
// fp32 -> (bf16 hi, bf16 lo) split conversion
// ---------------------------------------------------------------------------
__global__ void convert_kernel(const float* __restrict__ src, int which, int n4) {
    __nv_bfloat16 *hi, *lo;
    switch (which) {
        case 0: hi = g_xh;    lo = g_xl;    break;
        case 1: hi = g_Wh[0]; lo = g_Wl[0]; break;
        case 2: hi = g_Wh[1]; lo = g_Wl[1]; break;
        case 3: hi = g_Wh[2]; lo = g_Wl[2]; break;
        default: hi = g_Woh;  lo = g_Wol;   break;
    }
    int i = blockIdx.x * blockDim.x + threadIdx.x;
    if (i >= n4) return;
    float4 v = ((const float4*)src)[i];
    float vv[4] = {v.x, v.y, v.z, v.w};
#pragma unroll
    for (int t = 0; t < 4; t++) {
        __nv_bfloat16 h = __float2bfloat16(vv[t]);
        hi[4 * i + t] = h;
        lo[4 * i + t] = __float2bfloat16(vv[t] - __bfloat162float(h));
    }
}

// ---------------------------------------------------------------------------
// HMMA GEMM: C[128x128] = A @ B^T + bias, 3-term bf16 hi/lo split.
// MODE 0: qkv — writes bf16 hi/lo pairs to g_QKV*[z] in [b,h,t,hd]; Q scaled 1/8
// MODE 1: out projection (fp32 row-major [8192,1024])
// ---------------------------------------------------------------------------
template <int MODE>
__global__ void __launch_bounds__(256)
hmma_gemm_kernel(const float* __restrict__ b0, const float* __restrict__ b1,
                 const float* __restrict__ b2, float* __restrict__ outp) {
    extern __shared__ __nv_bfloat16 dsm[];
    const uint32_t sbase = smem_to_u32(dsm);
    const int tid = threadIdx.x;
    const int w = tid >> 5, lane = tid & 31;
    const int warp_m = w >> 2, warp_n = w & 3;   // 2 x 4 warp grid

    const __nv_bfloat16 *Ah, *Al, *Bh, *Bl;
    const float* bias;
    __nv_bfloat16 *dsth = nullptr, *dstl = nullptr;
    float qscale = 1.f;
    if (MODE == 0) {
        const int z = blockIdx.z;
        Ah = g_xh; Al = g_xl; Bh = g_Wh[z]; Bl = g_Wl[z];
        bias = (z == 0) ? b0 : (z == 1) ? b1 : b2;
        dsth = g_QKVh[z]; dstl = g_QKVl[z];
        if (z == 0) qscale = 0.125f;
    } else {
        Ah = g_ah; Al = g_al; Bh = g_Woh; Bl = g_Wol;
        bias = b0;
    }
    const int m0 = blockIdx.y * 128, n0 = blockIdx.x * 128;

    const __nv_bfloat16* gsrc[4] = {Ah, Al, Bh, Bl};
    const int rbase[4] = {m0, m0, n0, n0};

    float acc[4][4][4];
#pragma unroll
    for (int mi = 0; mi < 4; mi++)
#pragma unroll
        for (int ni = 0; ni < 4; ni++)
#pragma unroll
            for (int q = 0; q < 4; q++) acc[mi][ni][q] = 0.f;

    uint4 st[8];
    const int ld_row = tid >> 2;
    const int ld_q   = tid & 3;

#define LOAD_G(c)                                                               \
    {                                                                           \
        _Pragma("unroll")                                                       \
        for (int t4 = 0; t4 < 4; t4++) {                                        \
            _Pragma("unroll")                                                   \
            for (int it = 0; it < 2; it++) {                                    \
                const int row = ld_row + it * 64;                               \
                st[t4 * 2 + it] = *(const uint4*)(gsrc[t4] +                    \
                    (size_t)(rbase[t4] + row) * DN + (c) * KC + ld_q * 8);      \
            }                                                                   \
        }                                                                       \
    }
#define STORE_S(s)                                                              \
    {                                                                           \
        _Pragma("unroll")                                                       \
        for (int t4 = 0; t4 < 4; t4++) {                                        \
            _Pragma("unroll")                                                   \
            for (int it = 0; it < 2; it++) {                                    \
                const int row = ld_row + it * 64;                               \
                *(uint4*)(dsm + (size_t)(s) * STAGE_E + t4 * TILE_E +           \
                          row * ASTR + ld_q * 8) = st[t4 * 2 + it];             \
            }                                                                   \
        }                                                                       \
    }

    LOAD_G(0);
    STORE_S(0);
    __syncthreads();

    const int a_row = warp_m * 64 + (lane & 15);
    const int a_koff = ((lane >> 4) & 1) * 8;
    const int b_row = warp_n * 32 + (lane & 7);
    const int b_koff = ((lane >> 3) & 1) * 8;

    for (int c = 0; c < NCH; c++) {
        if (c + 1 < NCH) LOAD_G(c + 1);
        const uint32_t sb = sbase + (uint32_t)(c & 1) * (STAGE_E * 2);
#pragma unroll
        for (int ks = 0; ks < 2; ks++) {
            uint32_t ah[4][4], al[4][4], bh[4][2], bl[4][2];
#pragma unroll
            for (int mi = 0; mi < 4; mi++) {
                const uint32_t ad = sb +
                    (uint32_t)(((a_row + mi * 16) * ASTR + ks * 16 + a_koff) * 2);
                ldm_x4(ah[mi], ad);
                ldm_x4(al[mi], ad + TILE_E * 2);
            }
#pragma unroll
            for (int ni = 0; ni < 4; ni++) {
                const uint32_t bd = sb + 2 * TILE_E * 2 +
                    (uint32_t)(((b_row + ni * 8) * ASTR + ks * 16 + b_koff) * 2);
                asm volatile("ldmatrix.sync.aligned.m8n8.x2.shared.b16 {%0,%1}, [%2];"
                             : "=r"(bh[ni][0]), "=r"(bh[ni][1]) : "r"(bd));
                asm volatile("ldmatrix.sync.aligned.m8n8.x2.shared.b16 {%0,%1}, [%2];"
                             : "=r"(bl[ni][0]), "=r"(bl[ni][1]) : "r"(bd + TILE_E * 2));
            }
#pragma unroll
            for (int mi = 0; mi < 4; mi++)
#pragma unroll
                for (int ni = 0; ni < 4; ni++) {
                    mma_bf16(acc[mi][ni], ah[mi], bh[ni]);
                    mma_bf16(acc[mi][ni], ah[mi], bl[ni]);
                    mma_bf16(acc[mi][ni], al[mi], bh[ni]);
                }
        }
        __syncthreads();
        if (c + 1 < NCH) {
            STORE_S((c + 1) & 1);
            __syncthreads();
        }
    }

    const int g = lane >> 2;
    const int cp = (lane & 3) * 2;
#pragma unroll
    for (int mi = 0; mi < 4; mi++) {
#pragma unroll
        for (int ni = 0; ni < 4; ni++) {
            const int col = n0 + warp_n * 32 + ni * 8 + cp;
            const float bx = bias[col], by = bias[col + 1];
#pragma unroll
            for (int half = 0; half < 2; half++) {
                const int m = m0 + warp_m * 64 + mi * 16 + g + half * 8;
                float vx = acc[mi][ni][half * 2 + 0] + bx;
                float vy = acc[mi][ni][half * 2 + 1] + by;
                if (MODE == 0) {
                    vx *= qscale; vy *= qscale;
                    __nv_bfloat162 hp = __float22bfloat162_rn(make_float2(vx, vy));
                    float2 hf = __bfloat1622float2(hp);
                    __nv_bfloat162 lp = __float22bfloat162_rn(
                        make_float2(vx - hf.x, vy - hf.y));
                    const int b = m >> 11, t = m & (TN - 1);
                    const int hh = col >> 6, dh = col & 63;
                    const size_t off =
                        (((size_t)(b * HN + hh)) * TN + t) * HDN + dh;
                    *(__nv_bfloat162*)(dsth + off) = hp;
                    *(__nv_bfloat162*)(dstl + off) = lp;
                } else {
                    float2 v; v.x = vx; v.y = vy;
                    *(float2*)(outp + (size_t)m * DN + col) = v;
                }
            }
        }
    }
#undef LOAD_G
#undef STORE_S
}

// ---------------------------------------------------------------------------
// HMMA flash attention. CTA = (b,h, 128 q rows); 8 warps x m16 strips.
// S = QK^T (3-term split), fp32 online softmax in registers, P split hi/lo,
// O += PV (3-term, ldmatrix.trans V). Emits bf16 hi/lo for out projection.
// ---------------------------------------------------------------------------
__global__ void __launch_bounds__(256)
attn_kernel(const float* __restrict__ relbias) {
    extern __shared__ char smraw[];
    const uint32_t sbase = smem_to_u32(smraw);
    float* bsm = (float*)(smraw + 4 * ATILE_B);
    const int tid = threadIdx.x;
    const int w = tid >> 5, lane = tid & 31;
    const int g = lane >> 2, cq = lane & 3;
    const int bh = blockIdx.y, h = bh & (HN - 1);
    const int b_ = bh >> 4;
    const int q0 = blockIdx.x * QT;
    const int wrow = w * 16;

    if (tid < 31) bsm[tid] = relbias[tid * HN + h];

    // Stage Q tile (hi -> bytes [0, 2*ATILE_B), lo -> [2*ATILE_B, 4*ATILE_B))
    {
        const __nv_bfloat16* Qh = g_QKVh[0] + ((size_t)bh * TN + q0) * HDN;
        const __nv_bfloat16* Ql = g_QKVl[0] + ((size_t)bh * TN + q0) * HDN;
        uint4 t0[4], t1[4];
#pragma unroll
        for (int it = 0; it < 4; it++) {
            const int i = tid + it * 256, row = i >> 3, q = i & 7;
            t0[it] = *(const uint4*)(Qh + row * HDN + q * 8);
            t1[it] = *(const uint4*)(Ql + row * HDN + q * 8);
        }
#pragma unroll
        for (int it = 0; it < 4; it++) {
            const int i = tid + it * 256, row = i >> 3, q = i & 7;
            *(uint4*)(smraw + (row * 9 + q) * 16) = t0[it];
            *(uint4*)(smraw + 2 * ATILE_B + (row * 9 + q) * 16) = t1[it];
        }
    }
    __syncthreads();
    uint32_t qh[4][4], ql[4][4];
#pragma unroll
    for (int s = 0; s < 4; s++) {
        const uint32_t ad = sbase + (uint32_t)(
            ((wrow + (lane & 15)) * KSTR + ((lane >> 4) & 1) * 8 + s * 16) * 2);
        ldm_x4(qh[s], ad);
        ldm_x4(ql[s], ad + 2 * ATILE_B);
    }

    float o[8][4];
#pragma unroll
    for (int j = 0; j < 8; j++)
#pragma unroll
        for (int q = 0; q < 4; q++) o[j][q] = 0.f;
    float m_[2] = {-1e30f, -1e30f}, l_[2] = {0.f, 0.f};

    const __nv_bfloat16* gK[4] = {
        g_QKVh[1] + (size_t)bh * TN * HDN, g_QKVl[1] + (size_t)bh * TN * HDN,
        g_QKVh[2] + (size_t)bh * TN * HDN, g_QKVl[2] + (size_t)bh * TN * HDN};

    for (int kt = 0; kt < TN; kt += KTILE) {
        __syncthreads();       // prior iteration's ldmatrix reads done
        {
            uint4 tmp[8];
#pragma unroll
            for (int it = 0; it < 8; it++) {
                const int i = tid + it * 256;
                const int tile = i >> 9, j = i & 511, row = j >> 3, q = j & 7;
                tmp[it] = *(const uint4*)(gK[tile] + (size_t)(kt + row) * HDN + q * 8);
            }
#pragma unroll
            for (int it = 0; it < 8; it++) {
                const int i = tid + it * 256;
                const int tile = i >> 9, j = i & 511, row = j >> 3, q = j & 7;
                *(uint4*)(smraw + tile * ATILE_B + (row * 9 + q) * 16) = tmp[it];
            }
        }
        __syncthreads();

        // S = Q K^T  (Kh @ tile 0, Kl @ tile 1)
        float s_[8][4];
#pragma unroll
        for (int j = 0; j < 8; j++)
#pragma unroll
            for (int q = 0; q < 4; q++) s_[j][q] = 0.f;
#pragma unroll
        for (int s = 0; s < 4; s++) {
            uint32_t kh[4][4], kl[4][4];
#pragma unroll
            for (int jp = 0; jp < 4; jp++) {
                const uint32_t ad = sbase + (uint32_t)(
                    ((jp * 16 + ((lane >> 4) & 1) * 8 + (lane & 7)) * KSTR +
                     ((lane >> 3) & 1) * 8 + s * 16) * 2);
                ldm_x4(kh[jp], ad);
                ldm_x4(kl[jp], ad + ATILE_B);
            }
#pragma unroll
            for (int jp = 0; jp < 4; jp++) {
                mma_bf16(s_[2 * jp],     qh[s], kh[jp]);
                mma_bf16(s_[2 * jp],     qh[s], kl[jp]);
                mma_bf16(s_[2 * jp],     ql[s], kh[jp]);
                mma_bf16(s_[2 * jp + 1], qh[s], kh[jp] + 2);
                mma_bf16(s_[2 * jp + 1], qh[s], kl[jp] + 2);
                mma_bf16(s_[2 * jp + 1], ql[s], kh[jp] + 2);
            }
        }

        // Online softmax (fp32, registers)
#pragma unroll
        for (int r = 0; r < 2; r++) {
            const int qg = q0 + wrow + g + r * 8;
            float vmax = -1e30f;
#pragma unroll
            for (int j = 0; j < 8; j++)
#pragma unroll
                for (int e = 0; e < 2; e++) {
                    int rel = kt + j * 8 + cq * 2 + e - qg;
                    rel = rel < -15 ? -15 : (rel > 15 ? 15 : rel);
                    const float v = s_[j][r * 2 + e] + bsm[rel + 15];
                    s_[j][r * 2 + e] = v;
                    vmax = fmaxf(vmax, v);
                }
            vmax = fmaxf(vmax, __shfl_xor_sync(0xffffffffu, vmax, 1));
            vmax = fmaxf(vmax, __shfl_xor_sync(0xffffffffu, vmax, 2));
            const float nm = fmaxf(m_[r], vmax);
            const float scl = __expf(m_[r] - nm);
            m_[r] = nm;
            float rs = 0.f;
#pragma unroll
            for (int j = 0; j < 8; j++)
#pragma unroll
                for (int e = 0; e < 2; e++) {
                    const float p = __expf(s_[j][r * 2 + e] - nm);
                    s_[j][r * 2 + e] = p;
                    rs += p;
                }
            rs += __shfl_xor_sync(0xffffffffu, rs, 1);
            rs += __shfl_xor_sync(0xffffffffu, rs, 2);
            l_[r] = l_[r] * scl + rs;
#pragma unroll
            for (int j = 0; j < 8; j++) {
                o[j][r * 2 + 0] *= scl;
                o[j][r * 2 + 1] *= scl;
            }
        }

        // Pack P into bf16 hi/lo A-fragments (C-frag -> A-frag, no shuffles)
        uint32_t ph[4][4], pl[4][4];
#pragma unroll
        for (int j = 0; j < 8; j++) {
            __nv_bfloat162 h0 = __float22bfloat162_rn(make_float2(s_[j][0], s_[j][1]));
            float2 f0 = __bfloat1622float2(h0);
            __nv_bfloat162 l0 = __float22bfloat162_rn(
                make_float2(s_[j][0] - f0.x, s_[j][1] - f0.y));
            __nv_bfloat162 h1 = __float22bfloat162_rn(make_float2(s_[j][2], s_[j][3]));
            float2 f1 = __bfloat1622float2(h1);
            __nv_bfloat162 l1 = __float22bfloat162_rn(
                make_float2(s_[j][2] - f1.x, s_[j][3] - f1.y));
            const int s = j >> 1, hf = (j & 1) * 2;
            ph[s][hf + 0] = *(uint32_t*)&h0;
            ph[s][hf + 1] = *(uint32_t*)&h1;
            pl[s][hf + 0] = *(uint32_t*)&l0;
            pl[s][hf + 1] = *(uint32_t*)&l1;
        }

        // O += P V   (Vh @ tile 2, Vl @ tile 3; trans ldmatrix)
#pragma unroll
        for (int s = 0; s < 4; s++)
#pragma unroll
            for (int jv = 0; jv < 4; jv++) {
                uint32_t vh[4], vl[4];
                const uint32_t ad = sbase + 2 * ATILE_B + (uint32_t)(
                    ((s * 16 + ((lane >> 3) & 1) * 8 + (lane & 7)) * KSTR +
                     jv * 16 + ((lane >> 4) & 1) * 8) * 2);
                ldm_x4t(vh, ad);
                ldm_x4t(vl, ad + ATILE_B);
                mma_bf16(o[2 * jv],     ph[s], vh);
                mma_bf16(o[2 * jv],     pl[s], vh);
                mma_bf16(o[2 * jv],     ph[s], vl);
                mma_bf16(o[2 * jv + 1], ph[s], vh + 2);
                mma_bf16(o[2 * jv + 1], pl[s], vh + 2);
                mma_bf16(o[2 * jv + 1], ph[s], vl + 2);
            }
    }

    // Epilogue: normalize, split hi/lo, write [b,t,h*64+dh]
#pragma unroll
    for (int r = 0; r < 2; r++) {
        const float inv = 1.f / l_[r];
        const int t = q0 + wrow + g + r * 8;
        __nv_bfloat16* dh_ = g_ah + ((size_t)b_ * TN + t) * DN + h * HDN;
        __nv_bfloat16* dl_ = g_al + ((size_t)b_ * TN + t) * DN + h * HDN;
#pragma unroll
        for (int j = 0; j < 8; j++) {
            const float x = o[j][r * 2 + 0] * inv;
            const float y = o[j][r * 2 + 1] * inv;
            __nv_bfloat162 hp = __float22bfloat162_rn(make_float2(x, y));
            float2 hf2 = __bfloat1622float2(hp);
            __nv_bfloat162 lp = __float22bfloat162_rn(
                make_float2(x - hf2.x, y - hf2.y));
            *(__nv_bfloat162*)(dh_ + j * 8 + cq * 2) = hp;
            *(__nv_bfloat162*)(dl_ + j * 8 + cq * 2) = lp;
        }
    }
}

// ---------------------------------------------------------------------------
extern "C" void kernel_launch(void* const* d_in, const int* in_sizes, int n_in,
                              void* d_out, int out_size) {
    const float* x  = (const float*)d_in[0];
    const float* Wq = (const float*)d_in[1];
    const float* bq = (const float*)d_in[2];
    const float* Wk = (const float*)d_in[3];
    const float* bk = (const float*)d_in[4];
    const float* Wv = (const float*)d_in[5];
    const float* bv = (const float*)d_in[6];
    const float* rb = (const float*)d_in[7];
    const float* Wo = (const float*)d_in[8];
    const float* bo = (const float*)d_in[9];
    float* out = (float*)d_out;

    cudaFuncSetAttribute(hmma_gemm_kernel<0>,
                         cudaFuncAttributeMaxDynamicSharedMemorySize, SMEM_B);
    cudaFuncSetAttribute(hmma_gemm_kernel<1>,
                         cudaFuncAttributeMaxDynamicSharedMemorySize, SMEM_B);
    cudaFuncSetAttribute(attn_kernel,
                         cudaFuncAttributeMaxDynamicSharedMemorySize, ATTN_SMEM);

    // fp32 -> bf16 hi/lo splits
    convert_kernel<<<(MROWS * DN / 4 + 255) / 256, 256>>>(x, 0, MROWS * DN / 4);
    convert_kernel<<<(DN * DN / 4 + 255) / 256, 256>>>(Wq, 1, DN * DN / 4);
    convert_kernel<<<(DN * DN / 4 + 255) / 256, 256>>>(Wk, 2, DN * DN / 4);
    convert_kernel<<<(DN * DN / 4 + 255) / 256, 256>>>(Wv, 3, DN * DN / 4);
    convert_kernel<<<(DN * DN / 4 + 255) / 256, 256>>>(Wo, 4, DN * DN / 4);

    // QKV projections on HMMA (emit bf16 hi/lo, Q pre-scaled by 1/8)
    hmma_gemm_kernel<0><<<dim3(DN / 128, MROWS / 128, 3), 256, SMEM_B>>>(
        bq, bk, bv, nullptr);
    // HMMA flash attention
    attn_kernel<<<dim3(TN / QT, BN * HN), 256, ATTN_SMEM>>>(rb);
    // Output projection on HMMA
    hmma_gemm_kernel<1><<<dim3(DN / 128, MROWS / 128), 256, SMEM_B>>>(
        bo, nullptr, nullptr, out);
}

// round 7
// speedup vs baseline: 3.8634x; 1.3601x over previous
#include <cuda_runtime.h>
#include <cuda_bf16.h>
#include <cuda_fp16.h>
#include <cstdint>

// Problem constants
#define BN 4
#define TN 2048
#define DN 1024
#define HN 16
#define HDN 64
#define MROWS (BN * TN)   // 8192

// HMMA GEMM tiling: CTA 128x128, K-chunk 32, double-buffered smem
#define KC 32
#define NCH (DN / KC)          // 32
#define ASTR 40                // smem row stride in bf16 (32 data + 8 pad)
#define TILE_E (128 * ASTR)    // elems per 128x32 tile (padded)
#define STAGE_E (4 * TILE_E)   // Ah, Al, Bh, Bl
#define SMEM_B (2 * STAGE_E * 2)  // bytes (two stages)

// Attention tiling (fp16 single-pass)
#define QT 128                 // q rows per CTA
#define KTILE 64               // kv rows per iteration
#define KSTR 72                // smem row stride in halves (64 + 8 pad)
#define QSM_B (QT * KSTR * 2)      // 18432 B
#define KV_B (KTILE * KSTR * 2)    // 9216 B
#define ATTN_SMEM (QSM_B + 2 * KV_B + 128)

// ---------------------------------------------------------------------------
__device__ __forceinline__ uint32_t smem_to_u32(const void* p) {
    uint32_t a;
    asm("{ .reg .u64 t; cvta.to.shared.u64 t, %1; cvt.u32.u64 %0, t; }" : "=r"(a) : "l"(p));
    return a;
}
__device__ __forceinline__ void ldm_x4(uint32_t* r, uint32_t a) {
    asm volatile("ldmatrix.sync.aligned.m8n8.x4.shared.b16 {%0,%1,%2,%3}, [%4];"
                 : "=r"(r[0]), "=r"(r[1]), "=r"(r[2]), "=r"(r[3]) : "r"(a));
}
__device__ __forceinline__ void ldm_x4t(uint32_t* r, uint32_t a) {
    asm volatile("ldmatrix.sync.aligned.m8n8.x4.trans.shared.b16 {%0,%1,%2,%3}, [%4];"
                 : "=r"(r[0]), "=r"(r[1]), "=r"(r[2]), "=r"(r[3]) : "r"(a));
}
__device__ __forceinline__ void mma_bf16(float* c, const uint32_t* a, const uint32_t* b) {
    asm volatile(
        "mma.sync.aligned.m16n8k16.row.col.f32.bf16.bf16.f32 "
        "{%0,%1,%2,%3}, {%4,%5,%6,%7}, {%8,%9}, {%0,%1,%2,%3};"
        : "+f"(c[0]), "+f"(c[1]), "+f"(c[2]), "+f"(c[3])
        : "r"(a[0]), "r"(a[1]), "r"(a[2]), "r"(a[3]), "r"(b[0]), "r"(b[1]));
}
__device__ __forceinline__ void mma_f16(float* c, const uint32_t* a, const uint32_t* b) {
    asm volatile(
        "mma.sync.aligned.m16n8k16.row.col.f32.f16.f16.f32 "
        "{%0,%1,%2,%3}, {%4,%5,%6,%7}, {%8,%9}, {%0,%1,%2,%3};"
        : "+f"(c[0]), "+f"(c[1]), "+f"(c[2]), "+f"(c[3])
        : "r"(a[0]), "r"(a[1]), "r"(a[2]), "r"(a[3]), "r"(b[0]), "r"(b[1]));
}

// ---------------------------------------------------------------------------
// Device scratch (static: no runtime allocation allowed)
// ---------------------------------------------------------------------------
__device__ __nv_bfloat16 g_xh[(size_t)MROWS * DN];
__device__ __nv_bfloat16 g_xl[(size_t)MROWS * DN];
__device__ __nv_bfloat16 g_Wh[3][(size_t)DN * DN];   // Wq, Wk, Wv hi
__device__ __nv_bfloat16 g_Wl[3][(size_t)DN * DN];
__device__ __nv_bfloat16 g_Woh[(size_t)DN * DN];
__device__ __nv_bfloat16 g_Wol[(size_t)DN * DN];
__device__ __nv_bfloat16 g_ah[(size_t)MROWS * DN];   // attention output hi/lo
__device__ __nv_bfloat16 g_al[(size_t)MROWS * DN];
__device__ __half g_f16[3][(size_t)MROWS * DN];      // Q(pre-scaled)/K/V fp16 [b,h,t,hd]

// ---------------------------------------------------------------------------
// fp32 -> (bf16 hi, bf16 lo) split conversion
// ---------------------------------------------------------------------------
__global__ void convert_kernel(const float* __restrict__ src, int which, int n4) {
    __nv_bfloat16 *hi, *lo;
    switch (which) {
        case 0: hi = g_xh;    lo = g_xl;    break;
        case 1: hi = g_Wh[0]; lo = g_Wl[0]; break;
        case 2: hi = g_Wh[1]; lo = g_Wl[1]; break;
        case 3: hi = g_Wh[2]; lo = g_Wl[2]; break;
        default: hi = g_Woh;  lo = g_Wol;   break;
    }
    int i = blockIdx.x * blockDim.x + threadIdx.x;
    if (i >= n4) return;
    float4 v = ((const float4*)src)[i];
    float vv[4] = {v.x, v.y, v.z, v.w};
#pragma unroll
    for (int t = 0; t < 4; t++) {
        __nv_bfloat16 h = __float2bfloat16(vv[t]);
        hi[4 * i + t] = h;
        lo[4 * i + t] = __float2bfloat16(vv[t] - __bfloat162float(h));
    }
}

// ---------------------------------------------------------------------------
// HMMA GEMM: C[128x128] = A @ B^T + bias, 3-term bf16 hi/lo split.
// MODE 0: qkv — writes single fp16 to g_f16[z] in [b,h,t,hd]; Q scaled 1/8
// MODE 1: out projection (fp32 row-major [8192,1024])
// ---------------------------------------------------------------------------
template <int MODE>
__global__ void __launch_bounds__(256)
hmma_gemm_kernel(const float* __restrict__ b0, const float* __restrict__ b1,
                 const float* __restrict__ b2, float* __restrict__ outp) {
    extern __shared__ __nv_bfloat16 dsm[];
    const uint32_t sbase = smem_to_u32(dsm);
    const int tid = threadIdx.x;
    const int w = tid >> 5, lane = tid & 31;
    const int warp_m = w >> 2, warp_n = w & 3;   // 2 x 4 warp grid

    const __nv_bfloat16 *Ah, *Al, *Bh, *Bl;
    const float* bias;
    __half* dstf = nullptr;
    float qscale = 1.f;
    if (MODE == 0) {
        const int z = blockIdx.z;
        Ah = g_xh; Al = g_xl; Bh = g_Wh[z]; Bl = g_Wl[z];
        bias = (z == 0) ? b0 : (z == 1) ? b1 : b2;
        dstf = g_f16[z];
        if (z == 0) qscale = 0.125f;
    } else {
        Ah = g_ah; Al = g_al; Bh = g_Woh; Bl = g_Wol;
        bias = b0;
    }
    const int m0 = blockIdx.y * 128, n0 = blockIdx.x * 128;

    const __nv_bfloat16* gsrc[4] = {Ah, Al, Bh, Bl};
    const int rbase[4] = {m0, m0, n0, n0};

    float acc[4][4][4];
#pragma unroll
    for (int mi = 0; mi < 4; mi++)
#pragma unroll
        for (int ni = 0; ni < 4; ni++)
#pragma unroll
            for (int q = 0; q < 4; q++) acc[mi][ni][q] = 0.f;

    uint4 st[8];
    const int ld_row = tid >> 2;
    const int ld_q   = tid & 3;

#define LOAD_G(c)                                                               \
    {                                                                           \
        _Pragma("unroll")                                                       \
        for (int t4 = 0; t4 < 4; t4++) {                                        \
            _Pragma("unroll")                                                   \
            for (int it = 0; it < 2; it++) {                                    \
                const int row = ld_row + it * 64;                               \
                st[t4 * 2 + it] = *(const uint4*)(gsrc[t4] +                    \
                    (size_t)(rbase[t4] + row) * DN + (c) * KC + ld_q * 8);      \
            }                                                                   \
        }                                                                       \
    }
#define STORE_S(s)                                                              \
    {                                                                           \
        _Pragma("unroll")                                                       \
        for (int t4 = 0; t4 < 4; t4++) {                                        \
            _Pragma("unroll")                                                   \
            for (int it = 0; it < 2; it++) {                                    \
                const int row = ld_row + it * 64;                               \
                *(uint4*)(dsm + (size_t)(s) * STAGE_E + t4 * TILE_E +           \
                          row * ASTR + ld_q * 8) = st[t4 * 2 + it];             \
            }                                                                   \
        }                                                                       \
    }

    LOAD_G(0);
    STORE_S(0);
    __syncthreads();

    const int a_row = warp_m * 64 + (lane & 15);
    const int a_koff = ((lane >> 4) & 1) * 8;
    const int b_row = warp_n * 32 + (lane & 7);
    const int b_koff = ((lane >> 3) & 1) * 8;

    for (int c = 0; c < NCH; c++) {
        if (c + 1 < NCH) LOAD_G(c + 1);
        const uint32_t sb = sbase + (uint32_t)(c & 1) * (STAGE_E * 2);
#pragma unroll
        for (int ks = 0; ks < 2; ks++) {
            uint32_t ah[4][4], al[4][4], bh[4][2], bl[4][2];
#pragma unroll
            for (int mi = 0; mi < 4; mi++) {
                const uint32_t ad = sb +
                    (uint32_t)(((a_row + mi * 16) * ASTR + ks * 16 + a_koff) * 2);
                ldm_x4(ah[mi], ad);
                ldm_x4(al[mi], ad + TILE_E * 2);
            }
#pragma unroll
            for (int ni = 0; ni < 4; ni++) {
                const uint32_t bd = sb + 2 * TILE_E * 2 +
                    (uint32_t)(((b_row + ni * 8) * ASTR + ks * 16 + b_koff) * 2);
                asm volatile("ldmatrix.sync.aligned.m8n8.x2.shared.b16 {%0,%1}, [%2];"
                             : "=r"(bh[ni][0]), "=r"(bh[ni][1]) : "r"(bd));
                asm volatile("ldmatrix.sync.aligned.m8n8.x2.shared.b16 {%0,%1}, [%2];"
                             : "=r"(bl[ni][0]), "=r"(bl[ni][1]) : "r"(bd + TILE_E * 2));
            }
#pragma unroll
            for (int mi = 0; mi < 4; mi++)
#pragma unroll
                for (int ni = 0; ni < 4; ni++) {
                    mma_bf16(acc[mi][ni], ah[mi], bh[ni]);
                    mma_bf16(acc[mi][ni], ah[mi], bl[ni]);
                    mma_bf16(acc[mi][ni], al[mi], bh[ni]);
                }
        }
        __syncthreads();
        if (c + 1 < NCH) {
            STORE_S((c + 1) & 1);
            __syncthreads();
        }
    }

    const int g = lane >> 2;
    const int cp = (lane & 3) * 2;
#pragma unroll
    for (int mi = 0; mi < 4; mi++) {
#pragma unroll
        for (int ni = 0; ni < 4; ni++) {
            const int col = n0 + warp_n * 32 + ni * 8 + cp;
            const float bx = bias[col], by = bias[col + 1];
#pragma unroll
            for (int half = 0; half < 2; half++) {
                const int m = m0 + warp_m * 64 + mi * 16 + g + half * 8;
                float vx = acc[mi][ni][half * 2 + 0] + bx;
                float vy = acc[mi][ni][half * 2 + 1] + by;
                if (MODE == 0) {
                    vx *= qscale; vy *= qscale;
                    const __half2 hp = __floats2half2_rn(vx, vy);
                    const int b = m >> 11, t = m & (TN - 1);
                    const int hh = col >> 6, dh = col & 63;
                    *(__half2*)(dstf +
                        (((size_t)(b * HN + hh)) * TN + t) * HDN + dh) = hp;
                } else {
                    float2 v; v.x = vx; v.y = vy;
                    *(float2*)(outp + (size_t)m * DN + col) = v;
                }
            }
        }
    }
#undef LOAD_G
#undef STORE_S
}

// ---------------------------------------------------------------------------
// fp16 HMMA flash attention. CTA = (b,h, 128 q rows); 8 warps x m16 strips.
// Single-pass fp16 QK^T and PV; fp32 online softmax in registers.
// Register-staged K/V double buffering. Emits bf16 hi/lo for out projection.
// ---------------------------------------------------------------------------
__global__ void __launch_bounds__(256)
attn_kernel(const float* __restrict__ relbias) {
    extern __shared__ char smraw[];
    const uint32_t sbase = smem_to_u32(smraw);
    const uint32_t kbase = sbase + QSM_B;
    const uint32_t vbase = sbase + QSM_B + KV_B;
    float* bsm = (float*)(smraw + QSM_B + 2 * KV_B);
    const int tid = threadIdx.x;
    const int w = tid >> 5, lane = tid & 31;
    const int g = lane >> 2, cq = lane & 3;
    const int bh = blockIdx.y, h = bh & (HN - 1);
    const int b_ = bh >> 4;
    const int q0 = blockIdx.x * QT;
    const int wrow = w * 16;

    if (tid < 31) bsm[tid] = relbias[tid * HN + h];

    const __half* gQ = g_f16[0] + ((size_t)bh * TN + q0) * HDN;
    const __half* gK = g_f16[1] + (size_t)bh * TN * HDN;
    const __half* gV = g_f16[2] + (size_t)bh * TN * HDN;

    // Stage Q tile (128 rows x 64 halves, stride-72 rows)
#pragma unroll
    for (int it = 0; it < 4; it++) {
        const int i = tid + it * 256, row = i >> 3, q = i & 7;
        const uint4 v = *(const uint4*)(gQ + row * HDN + q * 8);
        *(uint4*)(smraw + (row * 9 + q) * 16) = v;
    }
    // Stage K/V tile 0 (tile 0 = K, tile 1 = V; 512 uint4 each)
    uint4 kv[4];
#pragma unroll
    for (int it = 0; it < 4; it++) {
        const int i = tid + it * 256;
        const int tile = i >> 9, j = i & 511, row = j >> 3, q = j & 7;
        const __half* src = tile ? gV : gK;
        kv[it] = *(const uint4*)(src + (size_t)row * HDN + q * 8);
    }
#pragma unroll
    for (int it = 0; it < 4; it++) {
        const int i = tid + it * 256;
        const int tile = i >> 9, j = i & 511, row = j >> 3, q = j & 7;
        *(uint4*)(smraw + QSM_B + tile * KV_B + (row * 9 + q) * 16) = kv[it];
    }
    __syncthreads();

    // Load Q fragments once
    uint32_t qf[4][4];
#pragma unroll
    for (int s = 0; s < 4; s++) {
        const uint32_t ad = sbase + (uint32_t)(
            ((wrow + (lane & 15)) * KSTR + ((lane >> 4) & 1) * 8 + s * 16) * 2);
        ldm_x4(qf[s], ad);
    }

    float o[8][4];
#pragma unroll
    for (int j = 0; j < 8; j++)
#pragma unroll
        for (int q = 0; q < 4; q++) o[j][q] = 0.f;
    float m_[2] = {-1e30f, -1e30f}, l_[2] = {0.f, 0.f};

    for (int kt = 0; kt < TN; kt += KTILE) {
        // Issue next tile's global loads (overlap with compute below)
        if (kt + KTILE < TN) {
#pragma unroll
            for (int it = 0; it < 4; it++) {
                const int i = tid + it * 256;
                const int tile = i >> 9, j = i & 511, row = j >> 3, q = j & 7;
                const __half* src = tile ? gV : gK;
                kv[it] = *(const uint4*)(src + (size_t)(kt + KTILE + row) * HDN + q * 8);
            }
        }

        // S = Q K^T (single-pass fp16)
        float s_[8][4];
#pragma unroll
        for (int j = 0; j < 8; j++)
#pragma unroll
            for (int q = 0; q < 4; q++) s_[j][q] = 0.f;
#pragma unroll
        for (int s = 0; s < 4; s++) {
            uint32_t kh[4][4];
#pragma unroll
            for (int jp = 0; jp < 4; jp++) {
                const uint32_t ad = kbase + (uint32_t)(
                    ((jp * 16 + ((lane >> 4) & 1) * 8 + (lane & 7)) * KSTR +
                     ((lane >> 3) & 1) * 8 + s * 16) * 2);
                ldm_x4(kh[jp], ad);
            }
#pragma unroll
            for (int jp = 0; jp < 4; jp++) {
                mma_f16(s_[2 * jp],     qf[s], kh[jp]);
                mma_f16(s_[2 * jp + 1], qf[s], kh[jp] + 2);
            }
        }

        // Online softmax (fp32, registers)
#pragma unroll
        for (int r = 0; r < 2; r++) {
            const int qg = q0 + wrow + g + r * 8;
            float vmax = -1e30f;
#pragma unroll
            for (int j = 0; j < 8; j++)
#pragma unroll
                for (int e = 0; e < 2; e++) {
                    int rel = kt + j * 8 + cq * 2 + e - qg;
                    rel = rel < -15 ? -15 : (rel > 15 ? 15 : rel);
                    const float v = s_[j][r * 2 + e] + bsm[rel + 15];
                    s_[j][r * 2 + e] = v;
                    vmax = fmaxf(vmax, v);
                }
            vmax = fmaxf(vmax, __shfl_xor_sync(0xffffffffu, vmax, 1));
            vmax = fmaxf(vmax, __shfl_xor_sync(0xffffffffu, vmax, 2));
            const float nm = fmaxf(m_[r], vmax);
            const float scl = __expf(m_[r] - nm);
            m_[r] = nm;
            float rs = 0.f;
#pragma unroll
            for (int j = 0; j < 8; j++)
#pragma unroll
                for (int e = 0; e < 2; e++) {
                    const float p = __expf(s_[j][r * 2 + e] - nm);
                    s_[j][r * 2 + e] = p;
                    rs += p;
                }
            rs += __shfl_xor_sync(0xffffffffu, rs, 1);
            rs += __shfl_xor_sync(0xffffffffu, rs, 2);
            l_[r] = l_[r] * scl + rs;
#pragma unroll
            for (int j = 0; j < 8; j++) {
                o[j][r * 2 + 0] *= scl;
                o[j][r * 2 + 1] *= scl;
            }
        }

        // Pack P into fp16 A-fragments (C-frag -> A-frag, no shuffles)
        uint32_t ph[4][4];
#pragma unroll
        for (int j = 0; j < 8; j++) {
            const __half2 h0 = __floats2half2_rn(s_[j][0], s_[j][1]);
            const __half2 h1 = __floats2half2_rn(s_[j][2], s_[j][3]);
            const int s = j >> 1, hf = (j & 1) * 2;
            ph[s][hf + 0] = *(const uint32_t*)&h0;
            ph[s][hf + 1] = *(const uint32_t*)&h1;
        }

        // O += P V (single-pass fp16, trans ldmatrix on V)
#pragma unroll
        for (int s = 0; s < 4; s++)
#pragma unroll
            for (int jv = 0; jv < 4; jv++) {
                uint32_t vh[4];
                const uint32_t ad = vbase + (uint32_t)(
                    ((s * 16 + ((lane >> 3) & 1) * 8 + (lane & 7)) * KSTR +
                     jv * 16 + ((lane >> 4) & 1) * 8) * 2);
                ldm_x4t(vh, ad);
                mma_f16(o[2 * jv],     ph[s], vh);
                mma_f16(o[2 * jv + 1], ph[s], vh + 2);
            }

        __syncthreads();               // ldmatrix reads done
        if (kt + KTILE < TN) {
#pragma unroll
            for (int it = 0; it < 4; it++) {
                const int i = tid + it * 256;
                const int tile = i >> 9, j = i & 511, row = j >> 3, q = j & 7;
                *(uint4*)(smraw + QSM_B + tile * KV_B + (row * 9 + q) * 16) = kv[it];
            }
            __syncthreads();
        }
    }

    // Epilogue: normalize, split hi/lo, write [b,t,h*64+dh]
#pragma unroll
    for (int r = 0; r < 2; r++) {
        const float inv = 1.f / l_[r];
        const int t = q0 + wrow + g + r * 8;
        __nv_bfloat16* dh_ = g_ah + ((size_t)b_ * TN + t) * DN + h * HDN;
        __nv_bfloat16* dl_ = g_al + ((size_t)b_ * TN + t) * DN + h * HDN;
#pragma unroll
        for (int j = 0; j < 8; j++) {
            const float x = o[j][r * 2 + 0] * inv;
            const float y = o[j][r * 2 + 1] * inv;
            __nv_bfloat162 hp = __float22bfloat162_rn(make_float2(x, y));
            float2 hf2 = __bfloat1622float2(hp);
            __nv_bfloat162 lp = __float22bfloat162_rn(
                make_float2(x - hf2.x, y - hf2.y));
            *(__nv_bfloat162*)(dh_ + j * 8 + cq * 2) = hp;
            *(__nv_bfloat162*)(dl_ + j * 8 + cq * 2) = lp;
        }
    }
}

// ---------------------------------------------------------------------------
extern "C" void kernel_launch(void* const* d_in, const int* in_sizes, int n_in,
                              void* d_out, int out_size) {
    const float* x  = (const float*)d_in[0];
    const float* Wq = (const float*)d_in[1];
    const float* bq = (const float*)d_in[2];
    const float* Wk = (const float*)d_in[3];
    const float* bk = (const float*)d_in[4];
    const float* Wv = (const float*)d_in[5];
    const float* bv = (const float*)d_in[6];
    const float* rb = (const float*)d_in[7];
    const float* Wo = (const float*)d_in[8];
    const float* bo = (const float*)d_in[9];
    float* out = (float*)d_out;

    cudaFuncSetAttribute(hmma_gemm_kernel<0>,
                         cudaFuncAttributeMaxDynamicSharedMemorySize, SMEM_B);
    cudaFuncSetAttribute(hmma_gemm_kernel<1>,
                         cudaFuncAttributeMaxDynamicSharedMemorySize, SMEM_B);
    cudaFuncSetAttribute(attn_kernel,
                         cudaFuncAttributeMaxDynamicSharedMemorySize, ATTN_SMEM);

    // fp32 -> bf16 hi/lo splits
    convert_kernel<<<(MROWS * DN / 4 + 255) / 256, 256>>>(x, 0, MROWS * DN / 4);
    convert_kernel<<<(DN * DN / 4 + 255) / 256, 256>>>(Wq, 1, DN * DN / 4);
    convert_kernel<<<(DN * DN / 4 + 255) / 256, 256>>>(Wk, 2, DN * DN / 4);
    convert_kernel<<<(DN * DN / 4 + 255) / 256, 256>>>(Wv, 3, DN * DN / 4);
    convert_kernel<<<(DN * DN / 4 + 255) / 256, 256>>>(Wo, 4, DN * DN / 4);

    // QKV projections on HMMA (bf16 3-term; emit fp16, Q pre-scaled by 1/8)
    hmma_gemm_kernel<0><<<dim3(DN / 128, MROWS / 128, 3), 256, SMEM_B>>>(
        bq, bk, bv, nullptr);
    // fp16 flash attention
    attn_kernel<<<dim3(TN / QT, BN * HN), 256, ATTN_SMEM>>>(rb);
    // Output projection on HMMA (bf16 3-term)
    hmma_gemm_kernel<1><<<dim3(DN / 128, MROWS / 128), 256, SMEM_B>>>(
        bo, nullptr, nullptr, out);
}

// round 9
// speedup vs baseline: 7.3320x; 1.8978x over previous
#include <cuda_runtime.h>
#include <cuda_bf16.h>
#include <cuda_fp16.h>
#include <cstdint>

// Problem constants
#define BN 4
#define TN 2048
#define DN 1024
#define HN 16
#define HDN 64
#define MROWS (BN * TN)   // 8192

// fp16 HMMA GEMM tiling: CTA 128x128, K-chunk 64, double-buffered smem
#define KC 64
#define NCH (DN / KC)          // 16
#define FSTR 72                // smem row stride in halves (64 + 8 pad)
#define FTILE_E (128 * FSTR)   // halves per 128x64 tile
#define FSTAGE_E (2 * FTILE_E) // A, B
#define FSMEM_B (2 * FSTAGE_E * 2)   // 73728 bytes (two stages)

// Attention tiling (fp16 single-pass)
#define QT 128                 // q rows per CTA
#define KTILE 64               // kv rows per iteration
#define KSTR 72                // smem row stride in halves
#define QSM_B (QT * KSTR * 2)      // 18432 B
#define KV_B (KTILE * KSTR * 2)    // 9216 B
#define ATTN_SMEM (QSM_B + 2 * KV_B + 128)

// ---------------------------------------------------------------------------
__device__ __forceinline__ uint32_t smem_to_u32(const void* p) {
    uint32_t a;
    asm("{ .reg .u64 t; cvta.to.shared.u64 t, %1; cvt.u32.u64 %0, t; }" : "=r"(a) : "l"(p));
    return a;
}
__device__ __forceinline__ void ldm_x4(uint32_t* r, uint32_t a) {
    asm volatile("ldmatrix.sync.aligned.m8n8.x4.shared.b16 {%0,%1,%2,%3}, [%4];"
                 : "=r"(r[0]), "=r"(r[1]), "=r"(r[2]), "=r"(r[3]) : "r"(a));
}
__device__ __forceinline__ void ldm_x2(uint32_t* r, uint32_t a) {
    asm volatile("ldmatrix.sync.aligned.m8n8.x2.shared.b16 {%0,%1}, [%2];"
                 : "=r"(r[0]), "=r"(r[1]) : "r"(a));
}
__device__ __forceinline__ void ldm_x4t(uint32_t* r, uint32_t a) {
    asm volatile("ldmatrix.sync.aligned.m8n8.x4.trans.shared.b16 {%0,%1,%2,%3}, [%4];"
                 : "=r"(r[0]), "=r"(r[1]), "=r"(r[2]), "=r"(r[3]) : "r"(a));
}
__device__ __forceinline__ void mma_f16(float* c, const uint32_t* a, const uint32_t* b) {
    asm volatile(
        "mma.sync.aligned.m16n8k16.row.col.f32.f16.f16.f32 "
        "{%0,%1,%2,%3}, {%4,%5,%6,%7}, {%8,%9}, {%0,%1,%2,%3};"
        : "+f"(c[0]), "+f"(c[1]), "+f"(c[2]), "+f"(c[3])
        : "r"(a[0]), "r"(a[1]), "r"(a[2]), "r"(a[3]), "r"(b[0]), "r"(b[1]));
}

// ---------------------------------------------------------------------------
// Device scratch (static: no runtime allocation allowed)
// ---------------------------------------------------------------------------
__device__ __half g_xf[(size_t)MROWS * DN];        // x in fp16
__device__ __half g_Wf[4][(size_t)DN * DN];        // Wq, Wk, Wv, Wo in fp16
__device__ __half g_qkv[3][(size_t)MROWS * DN];    // Q(/8)/K/V fp16 [b,h,t,hd]
__device__ __half g_att[(size_t)MROWS * DN];       // attention out fp16 [b,t,D]

// ---------------------------------------------------------------------------
// fp32 -> fp16 conversion
// ---------------------------------------------------------------------------
__global__ void convert_kernel(const float* __restrict__ src, int which, int n4) {
    __half* dst;
    switch (which) {
        case 0: dst = g_xf;    break;
        case 1: dst = g_Wf[0]; break;
        case 2: dst = g_Wf[1]; break;
        case 3: dst = g_Wf[2]; break;
        default: dst = g_Wf[3]; break;
    }
    int i = blockIdx.x * blockDim.x + threadIdx.x;
    if (i >= n4) return;
    float4 v = ((const float4*)src)[i];
    __half2 a = __floats2half2_rn(v.x, v.y);
    __half2 b = __floats2half2_rn(v.z, v.w);
    *(__half2*)(dst + 4 * i + 0) = a;
    *(__half2*)(dst + 4 * i + 2) = b;
}

// ---------------------------------------------------------------------------
// fp16 HMMA GEMM: C[128x128] = A @ B^T + bias (single-pass fp16, fp32 accum).
// MODE 0: qkv — writes fp16 to g_qkv[z] in [b,h,t,hd]; Q scaled 1/8
// MODE 1: out projection (fp32 row-major [8192,1024])
// ---------------------------------------------------------------------------
template <int MODE>
__global__ void __launch_bounds__(256)
hmma_gemm_kernel(const float* __restrict__ b0, const float* __restrict__ b1,
                 const float* __restrict__ b2, float* __restrict__ outp) {
    extern __shared__ __half dsm[];
    const uint32_t sbase = smem_to_u32(dsm);
    const int tid = threadIdx.x;
    const int w = tid >> 5, lane = tid & 31;
    const int warp_m = w >> 2, warp_n = w & 3;   // 2 x 4 warp grid

    const __half *A, *B;
    const float* bias;
    __half* dstf = nullptr;
    float qscale = 1.f;
    if (MODE == 0) {
        const int z = blockIdx.z;
        A = g_xf; B = g_Wf[z];
        bias = (z == 0) ? b0 : (z == 1) ? b1 : b2;
        dstf = g_qkv[z];
        if (z == 0) qscale = 0.125f;
    } else {
        A = g_att; B = g_Wf[3];
        bias = b0;
    }
    const int m0 = blockIdx.y * 128, n0 = blockIdx.x * 128;

    const __half* gsrc[2] = {A, B};
    const int rbase[2] = {m0, n0};

    float acc[4][4][4];
#pragma unroll
    for (int mi = 0; mi < 4; mi++)
#pragma unroll
        for (int ni = 0; ni < 4; ni++)
#pragma unroll
            for (int q = 0; q < 4; q++) acc[mi][ni][q] = 0.f;

    // per-chunk staging: 2 tiles x (128 rows x 8 uint4) / 256 thr = 8 uint4
    uint4 st[8];
    const int ld_row = tid >> 3;     // 0..31 (it adds 32)
    const int ld_q   = tid & 7;      // 16B unit within 128B row

#define LOAD_G(c)                                                               \
    {                                                                           \
        _Pragma("unroll")                                                       \
        for (int t2 = 0; t2 < 2; t2++) {                                        \
            _Pragma("unroll")                                                   \
            for (int it = 0; it < 4; it++) {                                    \
                const int row = ld_row + it * 32;                               \
                st[t2 * 4 + it] = *(const uint4*)(gsrc[t2] +                    \
                    (size_t)(rbase[t2] + row) * DN + (c) * KC + ld_q * 8);      \
            }                                                                   \
        }                                                                       \
    }
#define STORE_S(s)                                                              \
    {                                                                           \
        _Pragma("unroll")                                                       \
        for (int t2 = 0; t2 < 2; t2++) {                                        \
            _Pragma("unroll")                                                   \
            for (int it = 0; it < 4; it++) {                                    \
                const int row = ld_row + it * 32;                               \
                *(uint4*)(dsm + (size_t)(s) * FSTAGE_E + t2 * FTILE_E +         \
                          row * FSTR + ld_q * 8) = st[t2 * 4 + it];             \
            }                                                                   \
        }                                                                       \
    }

    LOAD_G(0);
    STORE_S(0);
    __syncthreads();

    const int a_row = warp_m * 64 + (lane & 15);
    const int a_koff = ((lane >> 4) & 1) * 8;
    const int b_row = warp_n * 32 + (lane & 7);
    const int b_koff = ((lane >> 3) & 1) * 8;

    for (int c = 0; c < NCH; c++) {
        if (c + 1 < NCH) LOAD_G(c + 1);
        const uint32_t sb = sbase + (uint32_t)(c & 1) * (FSTAGE_E * 2);
#pragma unroll
        for (int ks = 0; ks < 4; ks++) {
            uint32_t af[4][4], bf[4][2];
#pragma unroll
            for (int mi = 0; mi < 4; mi++) {
                const uint32_t ad = sb +
                    (uint32_t)(((a_row + mi * 16) * FSTR + ks * 16 + a_koff) * 2);
                ldm_x4(af[mi], ad);
            }
#pragma unroll
            for (int ni = 0; ni < 4; ni++) {
                const uint32_t bd = sb + FTILE_E * 2 +
                    (uint32_t)(((b_row + ni * 8) * FSTR + ks * 16 + b_koff) * 2);
                ldm_x2(bf[ni], bd);
            }
#pragma unroll
            for (int mi = 0; mi < 4; mi++)
#pragma unroll
                for (int ni = 0; ni < 4; ni++)
                    mma_f16(acc[mi][ni], af[mi], bf[ni]);
        }
        // Single sync per chunk: store targets the other buffer; the barrier
        // below also separates this chunk's reads from the next overwrite.
        if (c + 1 < NCH) {
            STORE_S((c + 1) & 1);
            __syncthreads();
        }
    }

    const int g = lane >> 2;
    const int cp = (lane & 3) * 2;
#pragma unroll
    for (int mi = 0; mi < 4; mi++) {
#pragma unroll
        for (int ni = 0; ni < 4; ni++) {
            const int col = n0 + warp_n * 32 + ni * 8 + cp;
            const float bx = bias[col], by = bias[col + 1];
#pragma unroll
            for (int half = 0; half < 2; half++) {
                const int m = m0 + warp_m * 64 + mi * 16 + g + half * 8;
                float vx = acc[mi][ni][half * 2 + 0] + bx;
                float vy = acc[mi][ni][half * 2 + 1] + by;
                if (MODE == 0) {
                    vx *= qscale; vy *= qscale;
                    const __half2 hp = __floats2half2_rn(vx, vy);
                    const int b = m >> 11, t = m & (TN - 1);
                    const int hh = col >> 6, dh = col & 63;
                    *(__half2*)(dstf +
                        (((size_t)(b * HN + hh)) * TN + t) * HDN + dh) = hp;
                } else {
                    float2 v; v.x = vx; v.y = vy;
                    *(float2*)(outp + (size_t)m * DN + col) = v;
                }
            }
        }
    }
#undef LOAD_G
#undef STORE_S
}

// ---------------------------------------------------------------------------
// fp16 HMMA flash attention. CTA = (b,h, 128 q rows); 8 warps x m16 strips.
// Single-pass fp16 QK^T and PV; fp32 online softmax in registers.
// Register-staged K/V double buffering. Emits fp16 [b,t,D] for out proj.
// ---------------------------------------------------------------------------
__global__ void __launch_bounds__(256)
attn_kernel(const float* __restrict__ relbias) {
    extern __shared__ char smraw[];
    const uint32_t sbase = smem_to_u32(smraw);
    const uint32_t kbase = sbase + QSM_B;
    const uint32_t vbase = sbase + QSM_B + KV_B;
    float* bsm = (float*)(smraw + QSM_B + 2 * KV_B);
    const int tid = threadIdx.x;
    const int w = tid >> 5, lane = tid & 31;
    const int g = lane >> 2, cq = lane & 3;
    const int bh = blockIdx.y, h = bh & (HN - 1);
    const int b_ = bh >> 4;
    const int q0 = blockIdx.x * QT;
    const int wrow = w * 16;

    if (tid < 31) bsm[tid] = relbias[tid * HN + h];

    const __half* gQ = g_qkv[0] + ((size_t)bh * TN + q0) * HDN;
    const __half* gK = g_qkv[1] + (size_t)bh * TN * HDN;
    const __half* gV = g_qkv[2] + (size_t)bh * TN * HDN;

    // Stage Q tile (128 rows x 64 halves, stride-72 rows)
#pragma unroll
    for (int it = 0; it < 4; it++) {
        const int i = tid + it * 256, row = i >> 3, q = i & 7;
        const uint4 v = *(const uint4*)(gQ + row * HDN + q * 8);
        *(uint4*)(smraw + (row * 9 + q) * 16) = v;
    }
    // Stage K/V tile 0 (tile 0 = K, tile 1 = V; 512 uint4 each)
    uint4 kv[4];
#pragma unroll
    for (int it = 0; it < 4; it++) {
        const int i = tid + it * 256;
        const int tile = i >> 9, j = i & 511, row = j >> 3, q = j & 7;
        const __half* src = tile ? gV : gK;
        kv[it] = *(const uint4*)(src + (size_t)row * HDN + q * 8);
    }
#pragma unroll
    for (int it = 0; it < 4; it++) {
        const int i = tid + it * 256;
        const int tile = i >> 9, j = i & 511, row = j >> 3, q = j & 7;
        *(uint4*)(smraw + QSM_B + tile * KV_B + (row * 9 + q) * 16) = kv[it];
    }
    __syncthreads();

    // Load Q fragments once
    uint32_t qf[4][4];
#pragma unroll
    for (int s = 0; s < 4; s++) {
        const uint32_t ad = sbase + (uint32_t)(
            ((wrow + (lane & 15)) * KSTR + ((lane >> 4) & 1) * 8 + s * 16) * 2);
        ldm_x4(qf[s], ad);
    }

    float o[8][4];
#pragma unroll
    for (int j = 0; j < 8; j++)
#pragma unroll
        for (int q = 0; q < 4; q++) o[j][q] = 0.f;
    float m_[2] = {-1e30f, -1e30f}, l_[2] = {0.f, 0.f};

    for (int kt = 0; kt < TN; kt += KTILE) {
        // Issue next tile's global loads (overlap with compute below)
        if (kt + KTILE < TN) {
#pragma unroll
            for (int it = 0; it < 4; it++) {
                const int i = tid + it * 256;
                const int tile = i >> 9, j = i & 511, row = j >> 3, q = j & 7;
                const __half* src = tile ? gV : gK;
                kv[it] = *(const uint4*)(src + (size_t)(kt + KTILE + row) * HDN + q * 8);
            }
        }

        // S = Q K^T (single-pass fp16)
        float s_[8][4];
#pragma unroll
        for (int j = 0; j < 8; j++)
#pragma unroll
            for (int q = 0; q < 4; q++) s_[j][q] = 0.f;
#pragma unroll
        for (int s = 0; s < 4; s++) {
            uint32_t kh[4][4];
#pragma unroll
            for (int jp = 0; jp < 4; jp++) {
                const uint32_t ad = kbase + (uint32_t)(
                    ((jp * 16 + ((lane >> 4) & 1) * 8 + (lane & 7)) * KSTR +
                     ((lane >> 3) & 1) * 8 + s * 16) * 2);
                ldm_x4(kh[jp], ad);
            }
#pragma unroll
            for (int jp = 0; jp < 4; jp++) {
                mma_f16(s_[2 * jp],     qf[s], kh[jp]);
                mma_f16(s_[2 * jp + 1], qf[s], kh[jp] + 2);
            }
        }

        // Online softmax (fp32, registers)
#pragma unroll
        for (int r = 0; r < 2; r++) {
            const int qg = q0 + wrow + g + r * 8;
            float vmax = -1e30f;
#pragma unroll
            for (int j = 0; j < 8; j++)
#pragma unroll
                for (int e = 0; e < 2; e++) {
                    int rel = kt + j * 8 + cq * 2 + e - qg;
                    rel = rel < -15 ? -15 : (rel > 15 ? 15 : rel);
                    const float v = s_[j][r * 2 + e] + bsm[rel + 15];
                    s_[j][r * 2 + e] = v;
                    vmax = fmaxf(vmax, v);
                }
            vmax = fmaxf(vmax, __shfl_xor_sync(0xffffffffu, vmax, 1));
            vmax = fmaxf(vmax, __shfl_xor_sync(0xffffffffu, vmax, 2));
            const float nm = fmaxf(m_[r], vmax);
            const float scl = __expf(m_[r] - nm);
            m_[r] = nm;
            float rs = 0.f;
#pragma unroll
            for (int j = 0; j < 8; j++)
#pragma unroll
                for (int e = 0; e < 2; e++) {
                    const float p = __expf(s_[j][r * 2 + e] - nm);
                    s_[j][r * 2 + e] = p;
                    rs += p;
                }
            rs += __shfl_xor_sync(0xffffffffu, rs, 1);
            rs += __shfl_xor_sync(0xffffffffu, rs, 2);
            l_[r] = l_[r] * scl + rs;
#pragma unroll
            for (int j = 0; j < 8; j++) {
                o[j][r * 2 + 0] *= scl;
                o[j][r * 2 + 1] *= scl;
            }
        }

        // Pack P into fp16 A-fragments (C-frag -> A-frag, no shuffles)
        uint32_t ph[4][4];
#pragma unroll
        for (int j = 0; j < 8; j++) {
            const __half2 h0 = __floats2half2_rn(s_[j][0], s_[j][1]);
            const __half2 h1 = __floats2half2_rn(s_[j][2], s_[j][3]);
            const int s = j >> 1, hf = (j & 1) * 2;
            ph[s][hf + 0] = *(const uint32_t*)&h0;
            ph[s][hf + 1] = *(const uint32_t*)&h1;
        }

        // O += P V (single-pass fp16, trans ldmatrix on V)
#pragma unroll
        for (int s = 0; s < 4; s++)
#pragma unroll
            for (int jv = 0; jv < 4; jv++) {
                uint32_t vh[4];
                const uint32_t ad = vbase + (uint32_t)(
                    ((s * 16 + ((lane >> 3) & 1) * 8 + (lane & 7)) * KSTR +
                     jv * 16 + ((lane >> 4) & 1) * 8) * 2);
                ldm_x4t(vh, ad);
                mma_f16(o[2 * jv],     ph[s], vh);
                mma_f16(o[2 * jv + 1], ph[s], vh + 2);
            }

        __syncthreads();               // ldmatrix reads done
        if (kt + KTILE < TN) {
#pragma unroll
            for (int it = 0; it < 4; it++) {
                const int i = tid + it * 256;
                const int tile = i >> 9, j = i & 511, row = j >> 3, q = j & 7;
                *(uint4*)(smraw + QSM_B + tile * KV_B + (row * 9 + q) * 16) = kv[it];
            }
            __syncthreads();
        }
    }

    // Epilogue: normalize, write fp16 [b,t,h*64+dh]
#pragma unroll
    for (int r = 0; r < 2; r++) {
        const float inv = 1.f / l_[r];
        const int t = q0 + wrow + g + r * 8;
        __half* d_ = g_att + ((size_t)b_ * TN + t) * DN + h * HDN;
#pragma unroll
        for (int j = 0; j < 8; j++) {
            const float x = o[j][r * 2 + 0] * inv;
            const float y = o[j][r * 2 + 1] * inv;
            *(__half2*)(d_ + j * 8 + cq * 2) = __floats2half2_rn(x, y);
        }
    }
}

// ---------------------------------------------------------------------------
extern "C" void kernel_launch(void* const* d_in, const int* in_sizes, int n_in,
                              void* d_out, int out_size) {
    const float* x  = (const float*)d_in[0];
    const float* Wq = (const float*)d_in[1];
    const float* bq = (const float*)d_in[2];
    const float* Wk = (const float*)d_in[3];
    const float* bk = (const float*)d_in[4];
    const float* Wv = (const float*)d_in[5];
    const float* bv = (const float*)d_in[6];
    const float* rb = (const float*)d_in[7];
    const float* Wo = (const float*)d_in[8];
    const float* bo = (const float*)d_in[9];
    float* out = (float*)d_out;

    cudaFuncSetAttribute(hmma_gemm_kernel<0>,
                         cudaFuncAttributeMaxDynamicSharedMemorySize, FSMEM_B);
    cudaFuncSetAttribute(hmma_gemm_kernel<1>,
                         cudaFuncAttributeMaxDynamicSharedMemorySize, FSMEM_B);
    cudaFuncSetAttribute(attn_kernel,
                         cudaFuncAttributeMaxDynamicSharedMemorySize, ATTN_SMEM);

    // fp32 -> fp16 converts
    convert_kernel<<<(MROWS * DN / 4 + 255) / 256, 256>>>(x, 0, MROWS * DN / 4);
    convert_kernel<<<(DN * DN / 4 + 255) / 256, 256>>>(Wq, 1, DN * DN / 4);
    convert_kernel<<<(DN * DN / 4 + 255) / 256, 256>>>(Wk, 2, DN * DN / 4);
    convert_kernel<<<(DN * DN / 4 + 255) / 256, 256>>>(Wv, 3, DN * DN / 4);
    convert_kernel<<<(DN * DN / 4 + 255) / 256, 256>>>(Wo, 4, DN * DN / 4);

    // QKV projections (single-pass fp16; emit fp16, Q pre-scaled by 1/8)
    hmma_gemm_kernel<0><<<dim3(DN / 128, MROWS / 128, 3), 256, FSMEM_B>>>(
        bq, bk, bv, nullptr);
    // fp16 flash attention
    attn_kernel<<<dim3(TN / QT, BN * HN), 256, ATTN_SMEM>>>(rb);
    // Output projection (single-pass fp16, fp32 out)
    hmma_gemm_kernel<1><<<dim3(DN / 128, MROWS / 128), 256, FSMEM_B>>>(
        bo, nullptr, nullptr, out);
}

// round 10
// speedup vs baseline: 9.0570x; 1.2353x over previous
#include <cuda_runtime.h>
#include <cuda_fp16.h>
#include <cstdint>

// Problem constants
#define BN 4
#define TN 2048
#define DN 1024
#define HN 16
#define HDN 64
#define MROWS (BN * TN)   // 8192

// fp16 HMMA GEMM tiling: CTA 128x128, K-chunk 64, cp.async double-buffered
#define KC 64
#define NCH (DN / KC)          // 16
#define FSTR 72                // smem row stride in halves (64 + 8 pad)
#define FTILE_E (128 * FSTR)   // halves per 128x64 tile
#define FSTAGE_E (2 * FTILE_E) // A, B
#define FSMEM_B (2 * FSTAGE_E * 2)   // 73728 bytes (two stages)

// Attention tiling (fp16 single-pass, cp.async double-buffered K/V)
#define QT 128                 // q rows per CTA
#define KTILE 64               // kv rows per iteration
#define NT (TN / KTILE)        // 32
#define KSTR 72                // smem row stride in halves
#define QSM_B (QT * KSTR * 2)      // 18432 B
#define KV_B (KTILE * KSTR * 2)    // 9216 B (one 64x64 tile)
#define ATTN_SMEM (QSM_B + 4 * KV_B + 128)   // Q + 2 stages x (K,V) + bias

// ---------------------------------------------------------------------------
__device__ __forceinline__ uint32_t smem_to_u32(const void* p) {
    uint32_t a;
    asm("{ .reg .u64 t; cvta.to.shared.u64 t, %1; cvt.u32.u64 %0, t; }" : "=r"(a) : "l"(p));
    return a;
}
__device__ __forceinline__ void ldm_x4(uint32_t* r, uint32_t a) {
    asm volatile("ldmatrix.sync.aligned.m8n8.x4.shared.b16 {%0,%1,%2,%3}, [%4];"
                 : "=r"(r[0]), "=r"(r[1]), "=r"(r[2]), "=r"(r[3]) : "r"(a));
}
__device__ __forceinline__ void ldm_x2(uint32_t* r, uint32_t a) {
    asm volatile("ldmatrix.sync.aligned.m8n8.x2.shared.b16 {%0,%1}, [%2];"
                 : "=r"(r[0]), "=r"(r[1]) : "r"(a));
}
__device__ __forceinline__ void ldm_x4t(uint32_t* r, uint32_t a) {
    asm volatile("ldmatrix.sync.aligned.m8n8.x4.trans.shared.b16 {%0,%1,%2,%3}, [%4];"
                 : "=r"(r[0]), "=r"(r[1]), "=r"(r[2]), "=r"(r[3]) : "r"(a));
}
__device__ __forceinline__ void mma_f16(float* c, const uint32_t* a, const uint32_t* b) {
    asm volatile(
        "mma.sync.aligned.m16n8k16.row.col.f32.f16.f16.f32 "
        "{%0,%1,%2,%3}, {%4,%5,%6,%7}, {%8,%9}, {%0,%1,%2,%3};"
        : "+f"(c[0]), "+f"(c[1]), "+f"(c[2]), "+f"(c[3])
        : "r"(a[0]), "r"(a[1]), "r"(a[2]), "r"(a[3]), "r"(b[0]), "r"(b[1]));
}
#define CP_ASYNC16(dst, src) \
    asm volatile("cp.async.cg.shared.global [%0], [%1], 16;" :: "r"(dst), "l"(src))
#define CP_COMMIT() asm volatile("cp.async.commit_group;")
#define CP_WAIT(n)  asm volatile("cp.async.wait_group %0;" :: "n"(n))

// ---------------------------------------------------------------------------
// Device scratch (static: no runtime allocation allowed)
// ---------------------------------------------------------------------------
__device__ __half g_xf[(size_t)MROWS * DN];        // x in fp16
__device__ __half g_Wf[4][(size_t)DN * DN];        // Wq, Wk, Wv, Wo in fp16
__device__ __half g_qkv[3][(size_t)MROWS * DN];    // Q(/8)/K/V fp16 [b,h,t,hd]
__device__ __half g_att[(size_t)MROWS * DN];       // attention out fp16 [b,t,D]

// ---------------------------------------------------------------------------
// Single fused fp32 -> fp16 conversion (x + 4 weight matrices, one launch)
// ---------------------------------------------------------------------------
#define XF4 (MROWS * DN / 4)   // 2097152
#define WF4 (DN * DN / 4)      // 262144
__global__ void convert_all_kernel(const float* __restrict__ x,
                                   const float* __restrict__ Wq,
                                   const float* __restrict__ Wk,
                                   const float* __restrict__ Wv,
                                   const float* __restrict__ Wo) {
    const int i = blockIdx.x * blockDim.x + threadIdx.x;
    const float* src;
    __half* dst;
    int off;
    if (i < XF4) {
        src = x; dst = g_xf; off = i;
    } else {
        const int j = i - XF4;
        const int w = j >> 18;            // / WF4
        off = j & (WF4 - 1);
        src = (w == 0) ? Wq : (w == 1) ? Wk : (w == 2) ? Wv : Wo;
        dst = g_Wf[w];
    }
    const float4 v = ((const float4*)src)[off];
    *(__half2*)(dst + 4 * off + 0) = __floats2half2_rn(v.x, v.y);
    *(__half2*)(dst + 4 * off + 2) = __floats2half2_rn(v.z, v.w);
}

// ---------------------------------------------------------------------------
// fp16 HMMA GEMM: C[128x128] = A @ B^T + bias (single-pass fp16, fp32 accum).
// cp.async double-buffered; 2 CTAs/SM target.
// MODE 0: qkv — writes fp16 to g_qkv[z] in [b,h,t,hd]; Q scaled 1/8
// MODE 1: out projection (fp32 row-major [8192,1024])
// ---------------------------------------------------------------------------
template <int MODE>
__global__ void __launch_bounds__(256, 2)
hmma_gemm_kernel(const float* __restrict__ b0, const float* __restrict__ b1,
                 const float* __restrict__ b2, float* __restrict__ outp) {
    extern __shared__ __half dsm[];
    const uint32_t sbase = smem_to_u32(dsm);
    const int tid = threadIdx.x;
    const int w = tid >> 5, lane = tid & 31;
    const int warp_m = w >> 2, warp_n = w & 3;   // 2 x 4 warp grid

    const __half *A, *B;
    const float* bias;
    __half* dstf = nullptr;
    float qscale = 1.f;
    if (MODE == 0) {
        const int z = blockIdx.z;
        A = g_xf; B = g_Wf[z];
        bias = (z == 0) ? b0 : (z == 1) ? b1 : b2;
        dstf = g_qkv[z];
        if (z == 0) qscale = 0.125f;
    } else {
        A = g_att; B = g_Wf[3];
        bias = b0;
    }
    const int m0 = blockIdx.y * 128, n0 = blockIdx.x * 128;

    const __half* gsrc[2] = {A, B};
    const int rbase[2] = {m0, n0};

    float acc[4][4][4];
#pragma unroll
    for (int mi = 0; mi < 4; mi++)
#pragma unroll
        for (int ni = 0; ni < 4; ni++)
#pragma unroll
            for (int q = 0; q < 4; q++) acc[mi][ni][q] = 0.f;

    const int ld_row = tid >> 3;     // 0..31 (it adds 32)
    const int ld_q   = tid & 7;      // 16B unit within 128B row

#define LOADSTAGE(s, c)                                                         \
    {                                                                           \
        _Pragma("unroll")                                                       \
        for (int t2 = 0; t2 < 2; t2++) {                                        \
            _Pragma("unroll")                                                   \
            for (int it = 0; it < 4; it++) {                                    \
                const int row = ld_row + it * 32;                               \
                const __half* gp = gsrc[t2] +                                   \
                    (size_t)(rbase[t2] + row) * DN + (c) * KC + ld_q * 8;       \
                const uint32_t sa = sbase + (uint32_t)((s) * FSTAGE_E +         \
                    t2 * FTILE_E + row * FSTR + ld_q * 8) * 2;                  \
                CP_ASYNC16(sa, gp);                                             \
            }                                                                   \
        }                                                                       \
        CP_COMMIT();                                                            \
    }

    LOADSTAGE(0, 0);

    const int a_row = warp_m * 64 + (lane & 15);
    const int a_koff = ((lane >> 4) & 1) * 8;
    const int b_row = warp_n * 32 + (lane & 7);
    const int b_koff = ((lane >> 3) & 1) * 8;

    for (int c = 0; c < NCH; c++) {
        if (c + 1 < NCH) {
            LOADSTAGE((c + 1) & 1, c + 1);
            CP_WAIT(1);
        } else {
            CP_WAIT(0);
        }
        __syncthreads();
        const uint32_t sb = sbase + (uint32_t)(c & 1) * (FSTAGE_E * 2);
#pragma unroll
        for (int ks = 0; ks < 4; ks++) {
            uint32_t af[4][4], bf[4][2];
#pragma unroll
            for (int mi = 0; mi < 4; mi++) {
                const uint32_t ad = sb +
                    (uint32_t)(((a_row + mi * 16) * FSTR + ks * 16 + a_koff) * 2);
                ldm_x4(af[mi], ad);
            }
#pragma unroll
            for (int ni = 0; ni < 4; ni++) {
                const uint32_t bd = sb + FTILE_E * 2 +
                    (uint32_t)(((b_row + ni * 8) * FSTR + ks * 16 + b_koff) * 2);
                ldm_x2(bf[ni], bd);
            }
#pragma unroll
            for (int mi = 0; mi < 4; mi++)
#pragma unroll
                for (int ni = 0; ni < 4; ni++)
                    mma_f16(acc[mi][ni], af[mi], bf[ni]);
        }
        __syncthreads();   // reads done before next cp.async overwrites
    }

    const int g = lane >> 2;
    const int cp = (lane & 3) * 2;
#pragma unroll
    for (int mi = 0; mi < 4; mi++) {
#pragma unroll
        for (int ni = 0; ni < 4; ni++) {
            const int col = n0 + warp_n * 32 + ni * 8 + cp;
            const float bx = bias[col], by = bias[col + 1];
#pragma unroll
            for (int half = 0; half < 2; half++) {
                const int m = m0 + warp_m * 64 + mi * 16 + g + half * 8;
                float vx = acc[mi][ni][half * 2 + 0] + bx;
                float vy = acc[mi][ni][half * 2 + 1] + by;
                if (MODE == 0) {
                    vx *= qscale; vy *= qscale;
                    const __half2 hp = __floats2half2_rn(vx, vy);
                    const int b = m >> 11, t = m & (TN - 1);
                    const int hh = col >> 6, dh = col & 63;
                    *(__half2*)(dstf +
                        (((size_t)(b * HN + hh)) * TN + t) * HDN + dh) = hp;
                } else {
                    float2 v; v.x = vx; v.y = vy;
                    *(float2*)(outp + (size_t)m * DN + col) = v;
                }
            }
        }
    }
#undef LOADSTAGE
}

// ---------------------------------------------------------------------------
// fp16 HMMA flash attention. CTA = (b,h, 128 q rows); 8 warps x m16 strips.
// cp.async double-buffered K/V; off-diagonal bias fast path.
// ---------------------------------------------------------------------------
__global__ void __launch_bounds__(256)
attn_kernel(const float* __restrict__ relbias) {
    extern __shared__ char smraw[];
    const uint32_t sbase = smem_to_u32(smraw);
    const uint32_t kvbase = sbase + QSM_B;      // stage s at kvbase + s*2*KV_B
    float* bsm = (float*)(smraw + QSM_B + 4 * KV_B);
    const int tid = threadIdx.x;
    const int w = tid >> 5, lane = tid & 31;
    const int g = lane >> 2, cq = lane & 3;
    const int bh = blockIdx.y, h = bh & (HN - 1);
    const int b_ = bh >> 4;
    const int q0 = blockIdx.x * QT;
    const int wrow = w * 16;

    if (tid < 31) bsm[tid] = relbias[tid * HN + h];

    const __half* gQ = g_qkv[0] + ((size_t)bh * TN + q0) * HDN;
    const __half* gK = g_qkv[1] + (size_t)bh * TN * HDN;
    const __half* gV = g_qkv[2] + (size_t)bh * TN * HDN;

    // KV stage loader: K -> tile 0, V -> tile 1 of stage s
#define KV_LOAD(s, kt_)                                                         \
    {                                                                           \
        _Pragma("unroll")                                                       \
        for (int it = 0; it < 4; it++) {                                        \
            const int i = tid + it * 256;                                       \
            const int tile = i >> 9, j = i & 511, row = j >> 3, q = j & 7;      \
            const __half* src = tile ? gV : gK;                                 \
            const uint32_t sa = kvbase + (uint32_t)((s) * 2 * KV_B +            \
                tile * KV_B + (row * 9 + q) * 16);                              \
            CP_ASYNC16(sa, src + (size_t)((kt_) + row) * HDN + q * 8);          \
        }                                                                       \
        CP_COMMIT();                                                            \
    }

    // Prologue: Q (group 0), KV tile 0 -> stage 0 (group 1)
#pragma unroll
    for (int it = 0; it < 4; it++) {
        const int i = tid + it * 256, row = i >> 3, q = i & 7;
        CP_ASYNC16(sbase + (uint32_t)((row * 9 + q) * 16), gQ + row * HDN + q * 8);
    }
    CP_COMMIT();
    KV_LOAD(0, 0);
    CP_WAIT(1);                 // Q resident
    __syncthreads();

    uint32_t qf[4][4];
#pragma unroll
    for (int s = 0; s < 4; s++) {
        const uint32_t ad = sbase + (uint32_t)(
            ((wrow + (lane & 15)) * KSTR + ((lane >> 4) & 1) * 8 + s * 16) * 2);
        ldm_x4(qf[s], ad);
    }
    const float blo = bsm[0], bhi = bsm[30];

    float o[8][4];
#pragma unroll
    for (int j = 0; j < 8; j++)
#pragma unroll
        for (int q = 0; q < 4; q++) o[j][q] = 0.f;
    float m_[2] = {-1e30f, -1e30f}, l_[2] = {0.f, 0.f};

    for (int ti = 0; ti < NT; ti++) {
        const int kt = ti * KTILE;
        if (ti + 1 < NT) {
            KV_LOAD((ti + 1) & 1, kt + KTILE);
            CP_WAIT(1);         // stage ti&1 complete
        } else {
            CP_WAIT(0);
        }
        __syncthreads();
        const uint32_t kb = kvbase + (uint32_t)(ti & 1) * (2 * KV_B);
        const uint32_t vb = kb + KV_B;

        // S = Q K^T (single-pass fp16)
        float s_[8][4];
#pragma unroll
        for (int j = 0; j < 8; j++)
#pragma unroll
            for (int q = 0; q < 4; q++) s_[j][q] = 0.f;
#pragma unroll
        for (int s = 0; s < 4; s++) {
            uint32_t kh[4][4];
#pragma unroll
            for (int jp = 0; jp < 4; jp++) {
                const uint32_t ad = kb + (uint32_t)(
                    ((jp * 16 + ((lane >> 4) & 1) * 8 + (lane & 7)) * KSTR +
                     ((lane >> 3) & 1) * 8 + s * 16) * 2);
                ldm_x4(kh[jp], ad);
            }
#pragma unroll
            for (int jp = 0; jp < 4; jp++) {
                mma_f16(s_[2 * jp],     qf[s], kh[jp]);
                mma_f16(s_[2 * jp + 1], qf[s], kh[jp] + 2);
            }
        }

        // Bias: fast path when the whole tile is outside the +/-15 band
        const bool fast_lo = (kt + 78) <= q0;          // all k - q <= -15
        const bool fast_hi = kt >= (q0 + QT + 14);     // all k - q >= +15
        if (fast_lo || fast_hi) {
            const float cb = fast_lo ? blo : bhi;
#pragma unroll
            for (int j = 0; j < 8; j++)
#pragma unroll
                for (int q = 0; q < 4; q++) s_[j][q] += cb;
        } else {
#pragma unroll
            for (int r = 0; r < 2; r++) {
                const int qg = q0 + wrow + g + r * 8;
#pragma unroll
                for (int j = 0; j < 8; j++)
#pragma unroll
                    for (int e = 0; e < 2; e++) {
                        int rel = kt + j * 8 + cq * 2 + e - qg;
                        rel = rel < -15 ? -15 : (rel > 15 ? 15 : rel);
                        s_[j][r * 2 + e] += bsm[rel + 15];
                    }
            }
        }

        // Online softmax (fp32, registers)
#pragma unroll
        for (int r = 0; r < 2; r++) {
            float vmax = -1e30f;
#pragma unroll
            for (int j = 0; j < 8; j++) {
                vmax = fmaxf(vmax, s_[j][r * 2 + 0]);
                vmax = fmaxf(vmax, s_[j][r * 2 + 1]);
            }
            vmax = fmaxf(vmax, __shfl_xor_sync(0xffffffffu, vmax, 1));
            vmax = fmaxf(vmax, __shfl_xor_sync(0xffffffffu, vmax, 2));
            const float nm = fmaxf(m_[r], vmax);
            const float scl = __expf(m_[r] - nm);
            m_[r] = nm;
            float rs = 0.f;
#pragma unroll
            for (int j = 0; j < 8; j++)
#pragma unroll
                for (int e = 0; e < 2; e++) {
                    const float p = __expf(s_[j][r * 2 + e] - nm);
                    s_[j][r * 2 + e] = p;
                    rs += p;
                }
            rs += __shfl_xor_sync(0xffffffffu, rs, 1);
            rs += __shfl_xor_sync(0xffffffffu, rs, 2);
            l_[r] = l_[r] * scl + rs;
#pragma unroll
            for (int j = 0; j < 8; j++) {
                o[j][r * 2 + 0] *= scl;
                o[j][r * 2 + 1] *= scl;
            }
        }

        // Pack P into fp16 A-fragments (C-frag -> A-frag, no shuffles)
        uint32_t ph[4][4];
#pragma unroll
        for (int j = 0; j < 8; j++) {
            const __half2 h0 = __floats2half2_rn(s_[j][0], s_[j][1]);
            const __half2 h1 = __floats2half2_rn(s_[j][2], s_[j][3]);
            const int s = j >> 1, hf = (j & 1) * 2;
            ph[s][hf + 0] = *(const uint32_t*)&h0;
            ph[s][hf + 1] = *(const uint32_t*)&h1;
        }

        // O += P V (single-pass fp16, trans ldmatrix on V)
#pragma unroll
        for (int s = 0; s < 4; s++)
#pragma unroll
            for (int jv = 0; jv < 4; jv++) {
                uint32_t vh[4];
                const uint32_t ad = vb + (uint32_t)(
                    ((s * 16 + ((lane >> 3) & 1) * 8 + (lane & 7)) * KSTR +
                     jv * 16 + ((lane >> 4) & 1) * 8) * 2);
                ldm_x4t(vh, ad);
                mma_f16(o[2 * jv],     ph[s], vh);
                mma_f16(o[2 * jv + 1], ph[s], vh + 2);
            }
        __syncthreads();   // stage reads done before next cp.async overwrite
    }

    // Epilogue: normalize, write fp16 [b,t,h*64+dh]
#pragma unroll
    for (int r = 0; r < 2; r++) {
        const float inv = 1.f / l_[r];
        const int t = q0 + wrow + g + r * 8;
        __half* d_ = g_att + ((size_t)b_ * TN + t) * DN + h * HDN;
#pragma unroll
        for (int j = 0; j < 8; j++) {
            const float x = o[j][r * 2 + 0] * inv;
            const float y = o[j][r * 2 + 1] * inv;
            *(__half2*)(d_ + j * 8 + cq * 2) = __floats2half2_rn(x, y);
        }
    }
#undef KV_LOAD
}

// ---------------------------------------------------------------------------
extern "C" void kernel_launch(void* const* d_in, const int* in_sizes, int n_in,
                              void* d_out, int out_size) {
    const float* x  = (const float*)d_in[0];
    const float* Wq = (const float*)d_in[1];
    const float* bq = (const float*)d_in[2];
    const float* Wk = (const float*)d_in[3];
    const float* bk = (const float*)d_in[4];
    const float* Wv = (const float*)d_in[5];
    const float* bv = (const float*)d_in[6];
    const float* rb = (const float*)d_in[7];
    const float* Wo = (const float*)d_in[8];
    const float* bo = (const float*)d_in[9];
    float* out = (float*)d_out;

    cudaFuncSetAttribute(hmma_gemm_kernel<0>,
                         cudaFuncAttributeMaxDynamicSharedMemorySize, FSMEM_B);
    cudaFuncSetAttribute(hmma_gemm_kernel<1>,
                         cudaFuncAttributeMaxDynamicSharedMemorySize, FSMEM_B);
    cudaFuncSetAttribute(attn_kernel,
                         cudaFuncAttributeMaxDynamicSharedMemorySize, ATTN_SMEM);

    // One fused fp32 -> fp16 convert (x + 4 weights)
    convert_all_kernel<<<(XF4 + 4 * WF4) / 256, 256>>>(x, Wq, Wk, Wv, Wo);

    // QKV projections (single-pass fp16; emit fp16, Q pre-scaled by 1/8)
    hmma_gemm_kernel<0><<<dim3(DN / 128, MROWS / 128, 3), 256, FSMEM_B>>>(
        bq, bk, bv, nullptr);
    // fp16 flash attention
    attn_kernel<<<dim3(TN / QT, BN * HN), 256, ATTN_SMEM>>>(rb);
    // Output projection (single-pass fp16, fp32 out)
    hmma_gemm_kernel<1><<<dim3(DN / 128, MROWS / 128), 256, FSMEM_B>>>(
        bo, nullptr, nullptr, out);
}

// round 11
// speedup vs baseline: 10.0001x; 1.1041x over previous
#include <cuda_runtime.h>
#include <cuda_fp16.h>
#include <cstdint>

// Problem constants
#define BN 4
#define TN 2048
#define DN 1024
#define HN 16
#define HDN 64
#define MROWS (BN * TN)   // 8192

// fp16 HMMA GEMM tiling: CTA 128x128, K-chunk 64, 3-stage cp.async, swizzled
#define KC 64
#define NCH (DN / KC)            // 16
#define FTILE_B 16384            // 128 rows x 128 B (swizzled, no pad)
#define FSTAGE_B (2 * FTILE_B)   // A tile + B tile
#define FSMEM_B (3 * FSTAGE_B)   // 98304 bytes (three stages)

// Attention tiling (fp16 single-pass, 3-stage cp.async K/V, swizzled)
#define QT 128                   // q rows per CTA
#define KTILE 64                 // kv rows per iteration
#define NT (TN / KTILE)          // 32
#define QSM_B (QT * 128)         // 16384 B
#define KVT_B (KTILE * 128)      // 8192 B per 64x64 tile
#define KVSTAGE_B (2 * KVT_B)    // K + V
#define ATTN_SMEM (QSM_B + 3 * KVSTAGE_B + 128)

// swizzle: 16B unit u at row -> u ^ (row & 7)
#define SWZ(row, u) ((row) * 128 + (((u) ^ ((row) & 7)) * 16))

// ---------------------------------------------------------------------------
__device__ __forceinline__ uint32_t smem_to_u32(const void* p) {
    uint32_t a;
    asm("{ .reg .u64 t; cvta.to.shared.u64 t, %1; cvt.u32.u64 %0, t; }" : "=r"(a) : "l"(p));
    return a;
}
__device__ __forceinline__ void ldm_x4(uint32_t* r, uint32_t a) {
    asm volatile("ldmatrix.sync.aligned.m8n8.x4.shared.b16 {%0,%1,%2,%3}, [%4];"
                 : "=r"(r[0]), "=r"(r[1]), "=r"(r[2]), "=r"(r[3]) : "r"(a));
}
__device__ __forceinline__ void ldm_x4t(uint32_t* r, uint32_t a) {
    asm volatile("ldmatrix.sync.aligned.m8n8.x4.trans.shared.b16 {%0,%1,%2,%3}, [%4];"
                 : "=r"(r[0]), "=r"(r[1]), "=r"(r[2]), "=r"(r[3]) : "r"(a));
}
__device__ __forceinline__ void mma_f16(float* c, const uint32_t* a, const uint32_t* b) {
    asm volatile(
        "mma.sync.aligned.m16n8k16.row.col.f32.f16.f16.f32 "
        "{%0,%1,%2,%3}, {%4,%5,%6,%7}, {%8,%9}, {%0,%1,%2,%3};"
        : "+f"(c[0]), "+f"(c[1]), "+f"(c[2]), "+f"(c[3])
        : "r"(a[0]), "r"(a[1]), "r"(a[2]), "r"(a[3]), "r"(b[0]), "r"(b[1]));
}
#define CP_ASYNC16(dst, src) \
    asm volatile("cp.async.cg.shared.global [%0], [%1], 16;" :: "r"(dst), "l"(src))
#define CP_COMMIT() asm volatile("cp.async.commit_group;")
#define CP_WAIT(n)  asm volatile("cp.async.wait_group %0;" :: "n"(n))

// ---------------------------------------------------------------------------
// Device scratch (static: no runtime allocation allowed)
// ---------------------------------------------------------------------------
__device__ __half g_xf[(size_t)MROWS * DN];        // x in fp16
__device__ __half g_Wf[4][(size_t)DN * DN];        // Wq, Wk, Wv, Wo in fp16
__device__ __half g_qkv[3][(size_t)MROWS * DN];    // Q(/8)/K/V fp16 [b,h,t,hd]
__device__ __half g_att[(size_t)MROWS * DN];       // attention out fp16 [b,t,D]

// ---------------------------------------------------------------------------
// Single fused fp32 -> fp16 conversion (x + 4 weight matrices, one launch)
// ---------------------------------------------------------------------------
#define XF4 (MROWS * DN / 4)   // 2097152
#define WF4 (DN * DN / 4)      // 262144
__global__ void convert_all_kernel(const float* __restrict__ x,
                                   const float* __restrict__ Wq,
                                   const float* __restrict__ Wk,
                                   const float* __restrict__ Wv,
                                   const float* __restrict__ Wo) {
    const int i = blockIdx.x * blockDim.x + threadIdx.x;
    const float* src;
    __half* dst;
    int off;
    if (i < XF4) {
        src = x; dst = g_xf; off = i;
    } else {
        const int j = i - XF4;
        const int w = j >> 18;            // / WF4
        off = j & (WF4 - 1);
        src = (w == 0) ? Wq : (w == 1) ? Wk : (w == 2) ? Wv : Wo;
        dst = g_Wf[w];
    }
    const float4 v = ((const float4*)src)[off];
    *(__half2*)(dst + 4 * off + 0) = __floats2half2_rn(v.x, v.y);
    *(__half2*)(dst + 4 * off + 2) = __floats2half2_rn(v.z, v.w);
}

// ---------------------------------------------------------------------------
// fp16 HMMA GEMM: C[128x128] = A @ B^T + bias (single-pass fp16, fp32 accum).
// 3-stage cp.async, swizzled smem, one barrier per chunk.
// MODE 0: qkv — writes fp16 to g_qkv[z] in [b,h,t,hd]; Q scaled 1/8
// MODE 1: out projection (fp32 row-major [8192,1024])
// ---------------------------------------------------------------------------
template <int MODE>
__global__ void __launch_bounds__(256, 2)
hmma_gemm_kernel(const float* __restrict__ b0, const float* __restrict__ b1,
                 const float* __restrict__ b2, float* __restrict__ outp) {
    extern __shared__ __half dsm[];
    const uint32_t sbase = smem_to_u32(dsm);
    const int tid = threadIdx.x;
    const int w = tid >> 5, lane = tid & 31;
    const int warp_m = w >> 2, warp_n = w & 3;   // 2 x 4 warp grid

    const __half *A, *B;
    const float* bias;
    __half* dstf = nullptr;
    float qscale = 1.f;
    if (MODE == 0) {
        const int z = blockIdx.z;
        A = g_xf; B = g_Wf[z];
        bias = (z == 0) ? b0 : (z == 1) ? b1 : b2;
        dstf = g_qkv[z];
        if (z == 0) qscale = 0.125f;
    } else {
        A = g_att; B = g_Wf[3];
        bias = b0;
    }
    const int m0 = blockIdx.y * 128, n0 = blockIdx.x * 128;

    const __half* gsrc[2] = {A, B};
    const int rbase[2] = {m0, n0};

    float acc[4][4][4];
#pragma unroll
    for (int mi = 0; mi < 4; mi++)
#pragma unroll
        for (int ni = 0; ni < 4; ni++)
#pragma unroll
            for (int q = 0; q < 4; q++) acc[mi][ni][q] = 0.f;

    const int ld_row = tid >> 3;     // 0..31 (it adds 32)
    const int ld_q   = tid & 7;      // 16B unit within 128B row

#define LOADSTAGE(s, c)                                                         \
    {                                                                           \
        _Pragma("unroll")                                                       \
        for (int t2 = 0; t2 < 2; t2++) {                                        \
            _Pragma("unroll")                                                   \
            for (int it = 0; it < 4; it++) {                                    \
                const int row = ld_row + it * 32;                               \
                const __half* gp = gsrc[t2] +                                   \
                    (size_t)(rbase[t2] + row) * DN + (c) * KC + ld_q * 8;       \
                const uint32_t sa = sbase + (uint32_t)((s) * FSTAGE_B +         \
                    t2 * FTILE_B + SWZ(row, ld_q));                             \
                CP_ASYNC16(sa, gp);                                             \
            }                                                                   \
        }                                                                       \
        CP_COMMIT();                                                            \
    }

    LOADSTAGE(0, 0);
    LOADSTAGE(1, 1);

    const int a_lrow = warp_m * 64 + (lane & 15);   // + mi*16
    const int a_u    = (lane >> 4) & 1;             // + ks*2
    const int b_lrow = warp_n * 32 + ((lane >> 4) << 3) + (lane & 7);  // + np*16
    const int b_u    = (lane >> 3) & 1;             // + ks*2

    for (int c = 0; c < NCH; c++) {
        if (c == NCH - 1) { CP_WAIT(0); } else { CP_WAIT(1); }
        __syncthreads();
        if (c + 2 < NCH) LOADSTAGE((c + 2) % 3, c + 2);
        const uint32_t sb = sbase + (uint32_t)(c % 3) * FSTAGE_B;
#pragma unroll
        for (int ks = 0; ks < 4; ks++) {
            uint32_t af[4][4], bf[2][4];
#pragma unroll
            for (int mi = 0; mi < 4; mi++) {
                const int row = a_lrow + mi * 16;
                ldm_x4(af[mi], sb + SWZ(row, ks * 2 + a_u));
            }
#pragma unroll
            for (int np = 0; np < 2; np++) {
                const int row = b_lrow + np * 16;
                ldm_x4(bf[np], sb + FTILE_B + SWZ(row, ks * 2 + b_u));
            }
#pragma unroll
            for (int mi = 0; mi < 4; mi++)
#pragma unroll
                for (int ni = 0; ni < 4; ni++)
                    mma_f16(acc[mi][ni], af[mi], bf[ni >> 1] + (ni & 1) * 2);
        }
    }

    const int g = lane >> 2;
    const int cp = (lane & 3) * 2;
#pragma unroll
    for (int mi = 0; mi < 4; mi++) {
#pragma unroll
        for (int ni = 0; ni < 4; ni++) {
            const int col = n0 + warp_n * 32 + ni * 8 + cp;
            const float bx = bias[col], by = bias[col + 1];
#pragma unroll
            for (int half = 0; half < 2; half++) {
                const int m = m0 + warp_m * 64 + mi * 16 + g + half * 8;
                float vx = acc[mi][ni][half * 2 + 0] + bx;
                float vy = acc[mi][ni][half * 2 + 1] + by;
                if (MODE == 0) {
                    vx *= qscale; vy *= qscale;
                    const __half2 hp = __floats2half2_rn(vx, vy);
                    const int b = m >> 11, t = m & (TN - 1);
                    const int hh = col >> 6, dh = col & 63;
                    *(__half2*)(dstf +
                        (((size_t)(b * HN + hh)) * TN + t) * HDN + dh) = hp;
                } else {
                    float2 v; v.x = vx; v.y = vy;
                    *(float2*)(outp + (size_t)m * DN + col) = v;
                }
            }
        }
    }
#undef LOADSTAGE
}

// ---------------------------------------------------------------------------
// fp16 HMMA flash attention. CTA = (b,h, 128 q rows); 8 warps x m16 strips.
// 3-stage cp.async K/V, swizzled smem, one barrier per tile.
// ---------------------------------------------------------------------------
__global__ void __launch_bounds__(256)
attn_kernel(const float* __restrict__ relbias) {
    extern __shared__ char smraw[];
    const uint32_t sbase = smem_to_u32(smraw);
    const uint32_t kvbase = sbase + QSM_B;      // stage s at kvbase + s*KVSTAGE_B
    float* bsm = (float*)(smraw + QSM_B + 3 * KVSTAGE_B);
    const int tid = threadIdx.x;
    const int w = tid >> 5, lane = tid & 31;
    const int g = lane >> 2, cq = lane & 3;
    const int bh = blockIdx.y, h = bh & (HN - 1);
    const int b_ = bh >> 4;
    const int q0 = blockIdx.x * QT;
    const int wrow = w * 16;

    if (tid < 31) bsm[tid] = relbias[tid * HN + h];

    const __half* gQ = g_qkv[0] + ((size_t)bh * TN + q0) * HDN;
    const __half* gK = g_qkv[1] + (size_t)bh * TN * HDN;
    const __half* gV = g_qkv[2] + (size_t)bh * TN * HDN;

    // KV stage loader: K -> tile 0, V -> tile 1 of stage s
#define KV_LOAD(s, kt_)                                                         \
    {                                                                           \
        _Pragma("unroll")                                                       \
        for (int it = 0; it < 4; it++) {                                        \
            const int i = tid + it * 256;                                       \
            const int tile = i >> 9, j = i & 511, row = j >> 3, q = j & 7;      \
            const __half* src = tile ? gV : gK;                                 \
            const uint32_t sa = kvbase + (uint32_t)((s) * KVSTAGE_B +           \
                tile * KVT_B + SWZ(row, q));                                    \
            CP_ASYNC16(sa, src + (size_t)((kt_) + row) * HDN + q * 8);          \
        }                                                                       \
        CP_COMMIT();                                                            \
    }

    // Prologue: Q (group 0), KV tiles 0,1 -> stages 0,1 (groups 1,2)
#pragma unroll
    for (int it = 0; it < 4; it++) {
        const int i = tid + it * 256, row = i >> 3, q = i & 7;
        CP_ASYNC16(sbase + (uint32_t)SWZ(row, q), gQ + row * HDN + q * 8);
    }
    CP_COMMIT();
    KV_LOAD(0, 0);
    KV_LOAD(1, KTILE);
    CP_WAIT(2);                 // Q resident
    __syncthreads();

    uint32_t qf[4][4];
#pragma unroll
    for (int s = 0; s < 4; s++) {
        const int row = wrow + (lane & 15);
        ldm_x4(qf[s], sbase + SWZ(row, s * 2 + ((lane >> 4) & 1)));
    }
    const float blo = bsm[0], bhi = bsm[30];

    float o[8][4];
#pragma unroll
    for (int j = 0; j < 8; j++)
#pragma unroll
        for (int q = 0; q < 4; q++) o[j][q] = 0.f;
    float m_[2] = {-1e30f, -1e30f}, l_[2] = {0.f, 0.f};

    for (int ti = 0; ti < NT; ti++) {
        const int kt = ti * KTILE;
        if (ti == NT - 1) { CP_WAIT(0); } else { CP_WAIT(1); }
        __syncthreads();
        if (ti + 2 < NT) KV_LOAD((ti + 2) % 3, kt + 2 * KTILE);
        const uint32_t kb = kvbase + (uint32_t)(ti % 3) * KVSTAGE_B;
        const uint32_t vb = kb + KVT_B;

        // S = Q K^T (single-pass fp16)
        float s_[8][4];
#pragma unroll
        for (int j = 0; j < 8; j++)
#pragma unroll
            for (int q = 0; q < 4; q++) s_[j][q] = 0.f;
#pragma unroll
        for (int s = 0; s < 4; s++) {
            uint32_t kh[4][4];
#pragma unroll
            for (int jp = 0; jp < 4; jp++) {
                const int row = jp * 16 + ((lane >> 4) << 3) + (lane & 7);
                ldm_x4(kh[jp], kb + SWZ(row, s * 2 + ((lane >> 3) & 1)));
            }
#pragma unroll
            for (int jp = 0; jp < 4; jp++) {
                mma_f16(s_[2 * jp],     qf[s], kh[jp]);
                mma_f16(s_[2 * jp + 1], qf[s], kh[jp] + 2);
            }
        }

        // Bias: fast path when the whole tile is outside the +/-15 band
        const bool fast_lo = (kt + 78) <= q0;          // all k - q <= -15
        const bool fast_hi = kt >= (q0 + QT + 14);     // all k - q >= +15
        if (fast_lo || fast_hi) {
            const float cb = fast_lo ? blo : bhi;
#pragma unroll
            for (int j = 0; j < 8; j++)
#pragma unroll
                for (int q = 0; q < 4; q++) s_[j][q] += cb;
        } else {
#pragma unroll
            for (int r = 0; r < 2; r++) {
                const int qg = q0 + wrow + g + r * 8;
#pragma unroll
                for (int j = 0; j < 8; j++)
#pragma unroll
                    for (int e = 0; e < 2; e++) {
                        int rel = kt + j * 8 + cq * 2 + e - qg;
                        rel = rel < -15 ? -15 : (rel > 15 ? 15 : rel);
                        s_[j][r * 2 + e] += bsm[rel + 15];
                    }
            }
        }

        // Online softmax (fp32, registers)
#pragma unroll
        for (int r = 0; r < 2; r++) {
            float vmax = -1e30f;
#pragma unroll
            for (int j = 0; j < 8; j++) {
                vmax = fmaxf(vmax, s_[j][r * 2 + 0]);
                vmax = fmaxf(vmax, s_[j][r * 2 + 1]);
            }
            vmax = fmaxf(vmax, __shfl_xor_sync(0xffffffffu, vmax, 1));
            vmax = fmaxf(vmax, __shfl_xor_sync(0xffffffffu, vmax, 2));
            const float nm = fmaxf(m_[r], vmax);
            const float scl = __expf(m_[r] - nm);
            m_[r] = nm;
            float rs = 0.f;
#pragma unroll
            for (int j = 0; j < 8; j++)
#pragma unroll
                for (int e = 0; e < 2; e++) {
                    const float p = __expf(s_[j][r * 2 + e] - nm);
                    s_[j][r * 2 + e] = p;
                    rs += p;
                }
            rs += __shfl_xor_sync(0xffffffffu, rs, 1);
            rs += __shfl_xor_sync(0xffffffffu, rs, 2);
            l_[r] = l_[r] * scl + rs;
#pragma unroll
            for (int j = 0; j < 8; j++) {
                o[j][r * 2 + 0] *= scl;
                o[j][r * 2 + 1] *= scl;
            }
        }

        // Pack P into fp16 A-fragments (C-frag -> A-frag, no shuffles)
        uint32_t ph[4][4];
#pragma unroll
        for (int j = 0; j < 8; j++) {
            const __half2 h0 = __floats2half2_rn(s_[j][0], s_[j][1]);
            const __half2 h1 = __floats2half2_rn(s_[j][2], s_[j][3]);
            const int s = j >> 1, hf = (j & 1) * 2;
            ph[s][hf + 0] = *(const uint32_t*)&h0;
            ph[s][hf + 1] = *(const uint32_t*)&h1;
        }

        // O += P V (single-pass fp16, trans ldmatrix on V)
#pragma unroll
        for (int s = 0; s < 4; s++)
#pragma unroll
            for (int jv = 0; jv < 4; jv++) {
                uint32_t vh[4];
                const int row = s * 16 + ((lane >> 3) & 1) * 8 + (lane & 7);
                ldm_x4t(vh, vb + SWZ(row, jv * 2 + ((lane >> 4) & 1)));
                mma_f16(o[2 * jv],     ph[s], vh);
                mma_f16(o[2 * jv + 1], ph[s], vh + 2);
            }
    }

    // Epilogue: normalize, write fp16 [b,t,h*64+dh]
#pragma unroll
    for (int r = 0; r < 2; r++) {
        const float inv = 1.f / l_[r];
        const int t = q0 + wrow + g + r * 8;
        __half* d_ = g_att + ((size_t)b_ * TN + t) * DN + h * HDN;
#pragma unroll
        for (int j = 0; j < 8; j++) {
            const float x = o[j][r * 2 + 0] * inv;
            const float y = o[j][r * 2 + 1] * inv;
            *(__half2*)(d_ + j * 8 + cq * 2) = __floats2half2_rn(x, y);
        }
    }
#undef KV_LOAD
}

// ---------------------------------------------------------------------------
extern "C" void kernel_launch(void* const* d_in, const int* in_sizes, int n_in,
                              void* d_out, int out_size) {
    const float* x  = (const float*)d_in[0];
    const float* Wq = (const float*)d_in[1];
    const float* bq = (const float*)d_in[2];
    const float* Wk = (const float*)d_in[3];
    const float* bk = (const float*)d_in[4];
    const float* Wv = (const float*)d_in[5];
    const float* bv = (const float*)d_in[6];
    const float* rb = (const float*)d_in[7];
    const float* Wo = (const float*)d_in[8];
    const float* bo = (const float*)d_in[9];
    float* out = (float*)d_out;

    cudaFuncSetAttribute(hmma_gemm_kernel<0>,
                         cudaFuncAttributeMaxDynamicSharedMemorySize, FSMEM_B);
    cudaFuncSetAttribute(hmma_gemm_kernel<1>,
                         cudaFuncAttributeMaxDynamicSharedMemorySize, FSMEM_B);
    cudaFuncSetAttribute(attn_kernel,
                         cudaFuncAttributeMaxDynamicSharedMemorySize, ATTN_SMEM);

    // One fused fp32 -> fp16 convert (x + 4 weights)
    convert_all_kernel<<<(XF4 + 4 * WF4) / 256, 256>>>(x, Wq, Wk, Wv, Wo);

    // QKV projections (single-pass fp16; emit fp16, Q pre-scaled by 1/8)
    hmma_gemm_kernel<0><<<dim3(DN / 128, MROWS / 128, 3), 256, FSMEM_B>>>(
        bq, bk, bv, nullptr);
    // fp16 flash attention
    attn_kernel<<<dim3(TN / QT, BN * HN), 256, ATTN_SMEM>>>(rb);
    // Output projection (single-pass fp16, fp32 out)
    hmma_gemm_kernel<1><<<dim3(DN / 128, MROWS / 128), 256, FSMEM_B>>>(
        bo, nullptr, nullptr, out);
}

// round 12
// speedup vs baseline: 10.0346x; 1.0034x over previous
#include <cuda_runtime.h>
#include <cuda_fp16.h>
#include <cstdint>

// Problem constants
#define BN 4
#define TN 2048
#define DN 1024
#define HN 16
#define HDN 64
#define MROWS (BN * TN)   // 8192

// fp16 HMMA GEMM tiling: CTA 128x128, K-chunk 64, 3-stage cp.async, swizzled
#define KC 64
#define NCH (DN / KC)            // 16
#define FTILE_B 16384            // 128 rows x 128 B (swizzled, no pad)
#define FSTAGE_B (2 * FTILE_B)   // A tile + B tile
#define FSMEM_B (3 * FSTAGE_B)   // 98304 bytes (three stages)

// Attention tiling (fp16 single-pass, 3-stage cp.async K/V, swizzled)
#define QT 128                   // q rows per CTA
#define KTILE 64                 // kv rows per iteration
#define NT (TN / KTILE)          // 32
#define QSM_B (QT * 128)         // 16384 B
#define KVT_B (KTILE * 128)      // 8192 B per 64x64 tile
#define KVSTAGE_B (2 * KVT_B)    // K + V
#define ATTN_SMEM (QSM_B + 3 * KVSTAGE_B + 128)

// swizzle: 16B unit u at row -> u ^ (row & 7)
#define SWZ(row, u) ((row) * 128 + (((u) ^ ((row) & 7)) * 16))

// ---------------------------------------------------------------------------
__device__ __forceinline__ uint32_t smem_to_u32(const void* p) {
    uint32_t a;
    asm("{ .reg .u64 t; cvta.to.shared.u64 t, %1; cvt.u32.u64 %0, t; }" : "=r"(a) : "l"(p));
    return a;
}
__device__ __forceinline__ void ldm_x4(uint32_t* r, uint32_t a) {
    asm volatile("ldmatrix.sync.aligned.m8n8.x4.shared.b16 {%0,%1,%2,%3}, [%4];"
                 : "=r"(r[0]), "=r"(r[1]), "=r"(r[2]), "=r"(r[3]) : "r"(a));
}
__device__ __forceinline__ void ldm_x4t(uint32_t* r, uint32_t a) {
    asm volatile("ldmatrix.sync.aligned.m8n8.x4.trans.shared.b16 {%0,%1,%2,%3}, [%4];"
                 : "=r"(r[0]), "=r"(r[1]), "=r"(r[2]), "=r"(r[3]) : "r"(a));
}
__device__ __forceinline__ void mma_f16(float* c, const uint32_t* a, const uint32_t* b) {
    asm volatile(
        "mma.sync.aligned.m16n8k16.row.col.f32.f16.f16.f32 "
        "{%0,%1,%2,%3}, {%4,%5,%6,%7}, {%8,%9}, {%0,%1,%2,%3};"
        : "+f"(c[0]), "+f"(c[1]), "+f"(c[2]), "+f"(c[3])
        : "r"(a[0]), "r"(a[1]), "r"(a[2]), "r"(a[3]), "r"(b[0]), "r"(b[1]));
}
#define CP_ASYNC16(dst, src) \
    asm volatile("cp.async.cg.shared.global [%0], [%1], 16;" :: "r"(dst), "l"(src))
#define CP_COMMIT() asm volatile("cp.async.commit_group;")
#define CP_WAIT(n)  asm volatile("cp.async.wait_group %0;" :: "n"(n))

// ---------------------------------------------------------------------------
// Device scratch (static: no runtime allocation allowed)
// ---------------------------------------------------------------------------
__device__ __half g_xf[(size_t)MROWS * DN];        // x in fp16
__device__ __half g_Wf[4][(size_t)DN * DN];        // Wq, Wk, Wv, Wo in fp16
__device__ __half g_qkv[3][(size_t)MROWS * DN];    // Q(/8)/K/V fp16 [b,h,t,hd]
__device__ __half g_att[(size_t)MROWS * DN];       // attention out fp16 [b,t,D]

// ---------------------------------------------------------------------------
// Single fused fp32 -> fp16 conversion (x + 4 weight matrices, one launch)
// ---------------------------------------------------------------------------
#define XF4 (MROWS * DN / 4)   // 2097152
#define WF4 (DN * DN / 4)      // 262144
__global__ void convert_all_kernel(const float* __restrict__ x,
                                   const float* __restrict__ Wq,
                                   const float* __restrict__ Wk,
                                   const float* __restrict__ Wv,
                                   const float* __restrict__ Wo) {
    const int i = blockIdx.x * blockDim.x + threadIdx.x;
    const float* src;
    __half* dst;
    int off;
    if (i < XF4) {
        src = x; dst = g_xf; off = i;
    } else {
        const int j = i - XF4;
        const int w = j >> 18;            // / WF4
        off = j & (WF4 - 1);
        src = (w == 0) ? Wq : (w == 1) ? Wk : (w == 2) ? Wv : Wo;
        dst = g_Wf[w];
    }
    const float4 v = ((const float4*)src)[off];
    *(__half2*)(dst + 4 * off + 0) = __floats2half2_rn(v.x, v.y);
    *(__half2*)(dst + 4 * off + 2) = __floats2half2_rn(v.z, v.w);
}

// ---------------------------------------------------------------------------
// fp16 HMMA GEMM: C[128x128] = A @ B^T + bias (single-pass fp16, fp32 accum).
// 3-stage cp.async, swizzled smem, fragment double-buffering (LDSM of ks+1
// overlaps mmas of ks, so smem crossbar and tensor pipe run concurrently).
// MODE 0: qkv — writes fp16 to g_qkv[z] in [b,h,t,hd]; Q scaled 1/8
// MODE 1: out projection (fp32 row-major [8192,1024])
// ---------------------------------------------------------------------------
template <int MODE>
__global__ void __launch_bounds__(256)
hmma_gemm_kernel(const float* __restrict__ b0, const float* __restrict__ b1,
                 const float* __restrict__ b2, float* __restrict__ outp) {
    extern __shared__ __half dsm[];
    const uint32_t sbase = smem_to_u32(dsm);
    const int tid = threadIdx.x;
    const int w = tid >> 5, lane = tid & 31;
    const int warp_m = w >> 2, warp_n = w & 3;   // 2 x 4 warp grid

    const __half *A, *B;
    const float* bias;
    __half* dstf = nullptr;
    float qscale = 1.f;
    if (MODE == 0) {
        const int z = blockIdx.z;
        A = g_xf; B = g_Wf[z];
        bias = (z == 0) ? b0 : (z == 1) ? b1 : b2;
        dstf = g_qkv[z];
        if (z == 0) qscale = 0.125f;
    } else {
        A = g_att; B = g_Wf[3];
        bias = b0;
    }
    const int m0 = blockIdx.y * 128, n0 = blockIdx.x * 128;

    const __half* gsrc[2] = {A, B};
    const int rbase[2] = {m0, n0};

    float acc[4][4][4];
#pragma unroll
    for (int mi = 0; mi < 4; mi++)
#pragma unroll
        for (int ni = 0; ni < 4; ni++)
#pragma unroll
            for (int q = 0; q < 4; q++) acc[mi][ni][q] = 0.f;

    const int ld_row = tid >> 3;     // 0..31 (it adds 32)
    const int ld_q   = tid & 7;      // 16B unit within 128B row

#define LOADSTAGE(s, c)                                                         \
    {                                                                           \
        _Pragma("unroll")                                                       \
        for (int t2 = 0; t2 < 2; t2++) {                                        \
            _Pragma("unroll")                                                   \
            for (int it = 0; it < 4; it++) {                                    \
                const int row = ld_row + it * 32;                               \
                const __half* gp = gsrc[t2] +                                   \
                    (size_t)(rbase[t2] + row) * DN + (c) * KC + ld_q * 8;       \
                const uint32_t sa = sbase + (uint32_t)((s) * FSTAGE_B +         \
                    t2 * FTILE_B + SWZ(row, ld_q));                             \
                CP_ASYNC16(sa, gp);                                             \
            }                                                                   \
        }                                                                       \
        CP_COMMIT();                                                            \
    }

    LOADSTAGE(0, 0);
    LOADSTAGE(1, 1);

    const int a_lrow = warp_m * 64 + (lane & 15);   // + mi*16
    const int a_u    = (lane >> 4) & 1;             // + ks*2
    const int b_lrow = warp_n * 32 + ((lane >> 4) << 3) + (lane & 7);  // + np*16
    const int b_u    = (lane >> 3) & 1;             // + ks*2

    uint32_t af[2][4][4], bf[2][2][4];

#define LDFRAG(buf, sb_, ks)                                                    \
    {                                                                           \
        _Pragma("unroll")                                                       \
        for (int mi = 0; mi < 4; mi++)                                          \
            ldm_x4(af[buf][mi], (sb_) + SWZ(a_lrow + mi * 16, (ks) * 2 + a_u)); \
        _Pragma("unroll")                                                       \
        for (int np = 0; np < 2; np++)                                          \
            ldm_x4(bf[buf][np],                                                 \
                   (sb_) + FTILE_B + SWZ(b_lrow + np * 16, (ks) * 2 + b_u));    \
    }

    for (int c = 0; c < NCH; c++) {
        if (c == NCH - 1) { CP_WAIT(0); } else { CP_WAIT(1); }
        __syncthreads();
        if (c + 2 < NCH) LOADSTAGE((c + 2) % 3, c + 2);
        const uint32_t sb = sbase + (uint32_t)(c % 3) * FSTAGE_B;
        LDFRAG(0, sb, 0);
#pragma unroll
        for (int ks = 0; ks < 4; ks++) {
            if (ks < 3) LDFRAG((ks + 1) & 1, sb, ks + 1);
            const int cur = ks & 1;
#pragma unroll
            for (int mi = 0; mi < 4; mi++)
#pragma unroll
                for (int ni = 0; ni < 4; ni++)
                    mma_f16(acc[mi][ni], af[cur][mi], bf[cur][ni >> 1] + (ni & 1) * 2);
        }
    }

    const int g = lane >> 2;
    const int cp = (lane & 3) * 2;
#pragma unroll
    for (int mi = 0; mi < 4; mi++) {
#pragma unroll
        for (int ni = 0; ni < 4; ni++) {
            const int col = n0 + warp_n * 32 + ni * 8 + cp;
            const float bx = bias[col], by = bias[col + 1];
#pragma unroll
            for (int half = 0; half < 2; half++) {
                const int m = m0 + warp_m * 64 + mi * 16 + g + half * 8;
                float vx = acc[mi][ni][half * 2 + 0] + bx;
                float vy = acc[mi][ni][half * 2 + 1] + by;
                if (MODE == 0) {
                    vx *= qscale; vy *= qscale;
                    const __half2 hp = __floats2half2_rn(vx, vy);
                    const int b = m >> 11, t = m & (TN - 1);
                    const int hh = col >> 6, dh = col & 63;
                    *(__half2*)(dstf +
                        (((size_t)(b * HN + hh)) * TN + t) * HDN + dh) = hp;
                } else {
                    float2 v; v.x = vx; v.y = vy;
                    *(float2*)(outp + (size_t)m * DN + col) = v;
                }
            }
        }
    }
#undef LOADSTAGE
#undef LDFRAG
}

// ---------------------------------------------------------------------------
// fp16 HMMA flash attention. CTA = (b,h, 128 q rows); 8 warps x m16 strips.
// 3-stage cp.async K/V, swizzled smem, fragment-pipelined QK and PV loops.
// ---------------------------------------------------------------------------
__global__ void __launch_bounds__(256)
attn_kernel(const float* __restrict__ relbias) {
    extern __shared__ char smraw[];
    const uint32_t sbase = smem_to_u32(smraw);
    const uint32_t kvbase = sbase + QSM_B;      // stage s at kvbase + s*KVSTAGE_B
    float* bsm = (float*)(smraw + QSM_B + 3 * KVSTAGE_B);
    const int tid = threadIdx.x;
    const int w = tid >> 5, lane = tid & 31;
    const int g = lane >> 2, cq = lane & 3;
    const int bh = blockIdx.y, h = bh & (HN - 1);
    const int b_ = bh >> 4;
    const int q0 = blockIdx.x * QT;
    const int wrow = w * 16;

    if (tid < 31) bsm[tid] = relbias[tid * HN + h];

    const __half* gQ = g_qkv[0] + ((size_t)bh * TN + q0) * HDN;
    const __half* gK = g_qkv[1] + (size_t)bh * TN * HDN;
    const __half* gV = g_qkv[2] + (size_t)bh * TN * HDN;

    // KV stage loader: K -> tile 0, V -> tile 1 of stage s
#define KV_LOAD(s, kt_)                                                         \
    {                                                                           \
        _Pragma("unroll")                                                       \
        for (int it = 0; it < 4; it++) {                                        \
            const int i = tid + it * 256;                                       \
            const int tile = i >> 9, j = i & 511, row = j >> 3, q = j & 7;      \
            const __half* src = tile ? gV : gK;                                 \
            const uint32_t sa = kvbase + (uint32_t)((s) * KVSTAGE_B +           \
                tile * KVT_B + SWZ(row, q));                                    \
            CP_ASYNC16(sa, src + (size_t)((kt_) + row) * HDN + q * 8);          \
        }                                                                       \
        CP_COMMIT();                                                            \
    }

    // Prologue: Q (group 0), KV tiles 0,1 -> stages 0,1 (groups 1,2)
#pragma unroll
    for (int it = 0; it < 4; it++) {
        const int i = tid + it * 256, row = i >> 3, q = i & 7;
        CP_ASYNC16(sbase + (uint32_t)SWZ(row, q), gQ + row * HDN + q * 8);
    }
    CP_COMMIT();
    KV_LOAD(0, 0);
    KV_LOAD(1, KTILE);
    CP_WAIT(2);                 // Q resident
    __syncthreads();

    uint32_t qf[4][4];
#pragma unroll
    for (int s = 0; s < 4; s++) {
        const int row = wrow + (lane & 15);
        ldm_x4(qf[s], sbase + SWZ(row, s * 2 + ((lane >> 4) & 1)));
    }
    const float blo = bsm[0], bhi = bsm[30];

    const int k_lrow = ((lane >> 4) << 3) + (lane & 7);   // + jp*16
    const int k_u    = (lane >> 3) & 1;                   // + s*2
    const int v_lrow = ((lane >> 3) & 1) * 8 + (lane & 7);  // + s*16
    const int v_u    = (lane >> 4) & 1;                   // + jv*2

    float o[8][4];
#pragma unroll
    for (int j = 0; j < 8; j++)
#pragma unroll
        for (int q = 0; q < 4; q++) o[j][q] = 0.f;
    float m_[2] = {-1e30f, -1e30f}, l_[2] = {0.f, 0.f};

    for (int ti = 0; ti < NT; ti++) {
        const int kt = ti * KTILE;
        if (ti == NT - 1) { CP_WAIT(0); } else { CP_WAIT(1); }
        __syncthreads();
        if (ti + 2 < NT) KV_LOAD((ti + 2) % 3, kt + 2 * KTILE);
        const uint32_t kb = kvbase + (uint32_t)(ti % 3) * KVSTAGE_B;
        const uint32_t vb = kb + KVT_B;

        // S = Q K^T — pipelined over flattened (s, jp); mma order preserved
        float s_[8][4];
#pragma unroll
        for (int j = 0; j < 8; j++)
#pragma unroll
            for (int q = 0; q < 4; q++) s_[j][q] = 0.f;
        {
            uint32_t kh[2][4];
            ldm_x4(kh[0], kb + SWZ(k_lrow, 0 * 2 + k_u));   // i=0: s=0, jp=0
#pragma unroll
            for (int i = 0; i < 16; i++) {
                const int s = i >> 2, jp = i & 3;
                if (i < 15) {
                    const int s2 = (i + 1) >> 2, jp2 = (i + 1) & 3;
                    ldm_x4(kh[(i + 1) & 1],
                           kb + SWZ(jp2 * 16 + k_lrow, s2 * 2 + k_u));
                }
                const int cur = i & 1;
                mma_f16(s_[2 * jp],     qf[s], kh[cur]);
                mma_f16(s_[2 * jp + 1], qf[s], kh[cur] + 2);
            }
        }

        // Bias: fast path when the whole tile is outside the +/-15 band
        const bool fast_lo = (kt + 78) <= q0;          // all k - q <= -15
        const bool fast_hi = kt >= (q0 + QT + 14);     // all k - q >= +15
        if (fast_lo || fast_hi) {
            const float cb = fast_lo ? blo : bhi;
#pragma unroll
            for (int j = 0; j < 8; j++)
#pragma unroll
                for (int q = 0; q < 4; q++) s_[j][q] += cb;
        } else {
#pragma unroll
            for (int r = 0; r < 2; r++) {
                const int qg = q0 + wrow + g + r * 8;
#pragma unroll
                for (int j = 0; j < 8; j++)
#pragma unroll
                    for (int e = 0; e < 2; e++) {
                        int rel = kt + j * 8 + cq * 2 + e - qg;
                        rel = rel < -15 ? -15 : (rel > 15 ? 15 : rel);
                        s_[j][r * 2 + e] += bsm[rel + 15];
                    }
            }
        }

        // Online softmax (fp32, registers)
#pragma unroll
        for (int r = 0; r < 2; r++) {
            float vmax = -1e30f;
#pragma unroll
            for (int j = 0; j < 8; j++) {
                vmax = fmaxf(vmax, s_[j][r * 2 + 0]);
                vmax = fmaxf(vmax, s_[j][r * 2 + 1]);
            }
            vmax = fmaxf(vmax, __shfl_xor_sync(0xffffffffu, vmax, 1));
            vmax = fmaxf(vmax, __shfl_xor_sync(0xffffffffu, vmax, 2));
            const float nm = fmaxf(m_[r], vmax);
            const float scl = __expf(m_[r] - nm);
            m_[r] = nm;
            float rs = 0.f;
#pragma unroll
            for (int j = 0; j < 8; j++)
#pragma unroll
                for (int e = 0; e < 2; e++) {
                    const float p = __expf(s_[j][r * 2 + e] - nm);
                    s_[j][r * 2 + e] = p;
                    rs += p;
                }
            rs += __shfl_xor_sync(0xffffffffu, rs, 1);
            rs += __shfl_xor_sync(0xffffffffu, rs, 2);
            l_[r] = l_[r] * scl + rs;
#pragma unroll
            for (int j = 0; j < 8; j++) {
                o[j][r * 2 + 0] *= scl;
                o[j][r * 2 + 1] *= scl;
            }
        }

        // Pack P into fp16 A-fragments (C-frag -> A-frag, no shuffles)
        uint32_t ph[4][4];
#pragma unroll
        for (int j = 0; j < 8; j++) {
            const __half2 h0 = __floats2half2_rn(s_[j][0], s_[j][1]);
            const __half2 h1 = __floats2half2_rn(s_[j][2], s_[j][3]);
            const int s = j >> 1, hf = (j & 1) * 2;
            ph[s][hf + 0] = *(const uint32_t*)&h0;
            ph[s][hf + 1] = *(const uint32_t*)&h1;
        }

        // O += P V — pipelined over flattened (s, jv); mma order preserved
        {
            uint32_t vh[2][4];
            ldm_x4t(vh[0], vb + SWZ(v_lrow, 0 * 2 + v_u));  // i=0: s=0, jv=0
#pragma unroll
            for (int i = 0; i < 16; i++) {
                const int s = i >> 2, jv = i & 3;
                if (i < 15) {
                    const int s2 = (i + 1) >> 2, jv2 = (i + 1) & 3;
                    ldm_x4t(vh[(i + 1) & 1],
                            vb + SWZ(s2 * 16 + v_lrow, jv2 * 2 + v_u));
                }
                const int cur = i & 1;
                mma_f16(o[2 * jv],     ph[s], vh[cur]);
                mma_f16(o[2 * jv + 1], ph[s], vh[cur] + 2);
            }
        }
    }

    // Epilogue: normalize, write fp16 [b,t,h*64+dh]
#pragma unroll
    for (int r = 0; r < 2; r++) {
        const float inv = 1.f / l_[r];
        const int t = q0 + wrow + g + r * 8;
        __half* d_ = g_att + ((size_t)b_ * TN + t) * DN + h * HDN;
#pragma unroll
        for (int j = 0; j < 8; j++) {
            const float x = o[j][r * 2 + 0] * inv;
            const float y = o[j][r * 2 + 1] * inv;
            *(__half2*)(d_ + j * 8 + cq * 2) = __floats2half2_rn(x, y);
        }
    }
#undef KV_LOAD
}

// ---------------------------------------------------------------------------
extern "C" void kernel_launch(void* const* d_in, const int* in_sizes, int n_in,
                              void* d_out, int out_size) {
    const float* x  = (const float*)d_in[0];
    const float* Wq = (const float*)d_in[1];
    const float* bq = (const float*)d_in[2];
    const float* Wk = (const float*)d_in[3];
    const float* bk = (const float*)d_in[4];
    const float* Wv = (const float*)d_in[5];
    const float* bv = (const float*)d_in[6];
    const float* rb = (const float*)d_in[7];
    const float* Wo = (const float*)d_in[8];
    const float* bo = (const float*)d_in[9];
    float* out = (float*)d_out;

    cudaFuncSetAttribute(hmma_gemm_kernel<0>,
                         cudaFuncAttributeMaxDynamicSharedMemorySize, FSMEM_B);
    cudaFuncSetAttribute(hmma_gemm_kernel<1>,
                         cudaFuncAttributeMaxDynamicSharedMemorySize, FSMEM_B);
    cudaFuncSetAttribute(attn_kernel,
                         cudaFuncAttributeMaxDynamicSharedMemorySize, ATTN_SMEM);

    // One fused fp32 -> fp16 convert (x + 4 weights)
    convert_all_kernel<<<(XF4 + 4 * WF4) / 256, 256>>>(x, Wq, Wk, Wv, Wo);

    // QKV projections (single-pass fp16; emit fp16, Q pre-scaled by 1/8)
    hmma_gemm_kernel<0><<<dim3(DN / 128, MROWS / 128, 3), 256, FSMEM_B>>>(
        bq, bk, bv, nullptr);
    // fp16 flash attention
    attn_kernel<<<dim3(TN / QT, BN * HN), 256, ATTN_SMEM>>>(rb);
    // Output projection (single-pass fp16, fp32 out)
    hmma_gemm_kernel<1><<<dim3(DN / 128, MROWS / 128), 256, FSMEM_B>>>(
        bo, nullptr, nullptr, out);
}